// round 10
// baseline (speedup 1.0000x reference)
#include <cuda_runtime.h>
#include <cuda_bf16.h>
#include <cstdint>

// Problem dims
#define BB  2
#define SS  2048
#define HH  1024
#define NHH 16
#define HDD 64
#define MM  (BB*SS)          // 4096 rows

// ---------------- scratch (no cudaMalloc allowed) ----------------
__device__ __nv_bfloat16 g_a2[MM * 2048];        // hi|lo split, [row][0:1024 hi | 1024:2048 lo]
__device__ __nv_bfloat16 g_wq2[HH * 2048];
__device__ __nv_bfloat16 g_wk2[HH * 2048];
__device__ __nv_bfloat16 g_wv2[HH * 2048];
__device__ __nv_bfloat16 g_wo2[HH * 2048];
// per-head split layout: [row][h*128 + (0:64 hi | 64:128 lo)]
__device__ __nv_bfloat16 g_q2[MM * 2048];
__device__ __nv_bfloat16 g_k2[MM * 2048];
__device__ __nv_bfloat16 g_v2[MM * 2048];

// ================= PTX helpers (non-'a' features only) =================
__device__ __forceinline__ uint32_t smem_u32(const void* p) {
    uint32_t a;
    asm("{ .reg .u64 t; cvta.to.shared.u64 t, %1; cvt.u32.u64 %0, t; }" : "=r"(a) : "l"(p));
    return a;
}
__device__ __forceinline__ void cp16(uint32_t dst, const void* src) {
    asm volatile("cp.async.cg.shared.global [%0], [%1], 16;" :: "r"(dst), "l"(src));
}
__device__ __forceinline__ void cp_commit() {
    asm volatile("cp.async.commit_group;" ::: "memory");
}
template<int N> __device__ __forceinline__ void cp_wait() {
    asm volatile("cp.async.wait_group %0;" :: "n"(N) : "memory");
}
__device__ __forceinline__ void ldmat4(uint32_t& r0, uint32_t& r1, uint32_t& r2, uint32_t& r3,
                                       uint32_t addr) {
    asm volatile("ldmatrix.sync.aligned.m8n8.x4.shared.b16 {%0,%1,%2,%3}, [%4];"
                 : "=r"(r0), "=r"(r1), "=r"(r2), "=r"(r3) : "r"(addr));
}
__device__ __forceinline__ void ldmat4t(uint32_t& r0, uint32_t& r1, uint32_t& r2, uint32_t& r3,
                                        uint32_t addr) {
    asm volatile("ldmatrix.sync.aligned.m8n8.x4.trans.shared.b16 {%0,%1,%2,%3}, [%4];"
                 : "=r"(r0), "=r"(r1), "=r"(r2), "=r"(r3) : "r"(addr));
}
__device__ __forceinline__ void mma16816(float* d, uint32_t a0, uint32_t a1, uint32_t a2,
                                         uint32_t a3, uint32_t b0, uint32_t b1) {
    asm volatile("mma.sync.aligned.m16n8k16.row.col.f32.bf16.bf16.f32 "
                 "{%0,%1,%2,%3},{%4,%5,%6,%7},{%8,%9},{%0,%1,%2,%3};"
                 : "+f"(d[0]), "+f"(d[1]), "+f"(d[2]), "+f"(d[3])
                 : "r"(a0), "r"(a1), "r"(a2), "r"(a3), "r"(b0), "r"(b1));
}
__device__ __forceinline__ uint32_t pack_bf2(float x, float y) {
    __nv_bfloat162 t;
    t.x = __float2bfloat16_rn(x);
    t.y = __float2bfloat16_rn(y);
    return *(uint32_t*)&t;
}

// ================= splits =================
__global__ void split_kernel(const float* __restrict__ a, const float* __restrict__ b,
                             __nv_bfloat16* __restrict__ out) {
    int i = blockIdx.x * 256 + threadIdx.x;
    int r = i >> 8;
    int c4 = (i & 255) << 2;
    float4 x = ((const float4*)a)[i];
    if (b) {
        float4 y = ((const float4*)b)[i];
        x.x += y.x; x.y += y.y; x.z += y.z; x.w += y.w;
    }
    float vf[4] = {x.x, x.y, x.z, x.w};
    __nv_bfloat16 h[4], l[4];
#pragma unroll
    for (int j = 0; j < 4; j++) {
        h[j] = __float2bfloat16_rn(vf[j]);
        l[j] = __float2bfloat16_rn(vf[j] - __bfloat162float(h[j]));
    }
    __nv_bfloat16* o = out + (size_t)r * 2048 + c4;
    ((__nv_bfloat162*)o)[0] = __halves2bfloat162(h[0], h[1]);
    ((__nv_bfloat162*)o)[1] = __halves2bfloat162(h[2], h[3]);
    ((__nv_bfloat162*)(o + 1024))[0] = __halves2bfloat162(l[0], l[1]);
    ((__nv_bfloat162*)(o + 1024))[1] = __halves2bfloat162(l[2], l[3]);
}

// fused 4-weight split: grid (1024, 4)
__global__ void wsplit4_kernel(const float* __restrict__ s0, const float* __restrict__ d0,
                               const float* __restrict__ s1, const float* __restrict__ d1,
                               const float* __restrict__ s2, const float* __restrict__ d2,
                               const float* __restrict__ s3, const float* __restrict__ d3,
                               __nv_bfloat16* __restrict__ o0, __nv_bfloat16* __restrict__ o1,
                               __nv_bfloat16* __restrict__ o2, __nv_bfloat16* __restrict__ o3) {
    const int w = blockIdx.y;
    const float* a = (w == 0) ? s0 : (w == 1) ? s1 : (w == 2) ? s2 : s3;
    const float* b = (w == 0) ? d0 : (w == 1) ? d1 : (w == 2) ? d2 : d3;
    __nv_bfloat16* out = (w == 0) ? o0 : (w == 1) ? o1 : (w == 2) ? o2 : o3;

    int i = blockIdx.x * 256 + threadIdx.x;
    int r = i >> 8;
    int c4 = (i & 255) << 2;
    float4 x = ((const float4*)a)[i];
    float4 y = ((const float4*)b)[i];
    x.x += y.x; x.y += y.y; x.z += y.z; x.w += y.w;
    float vf[4] = {x.x, x.y, x.z, x.w};
    __nv_bfloat16 h[4], l[4];
#pragma unroll
    for (int j = 0; j < 4; j++) {
        h[j] = __float2bfloat16_rn(vf[j]);
        l[j] = __float2bfloat16_rn(vf[j] - __bfloat162float(h[j]));
    }
    __nv_bfloat16* o = out + (size_t)r * 2048 + c4;
    ((__nv_bfloat162*)o)[0] = __halves2bfloat162(h[0], h[1]);
    ((__nv_bfloat162*)o)[1] = __halves2bfloat162(h[2], h[3]);
    ((__nv_bfloat162*)(o + 1024))[0] = __halves2bfloat162(l[0], l[1]);
    ((__nv_bfloat162*)(o + 1024))[1] = __halves2bfloat162(l[2], l[3]);
}

// ================= HMMA split-bf16 GEMM =================
// K-chunk 128 (24 chunks), 128 MMAs per barrier, 3-stage cp.async, occ 1, 8 warps.
// 272B padded rows (17 x 16B units, odd -> conflict-free for ldmatrix).
#define GROWB 272
#define GTILEB (128 * GROWB)             // 34816
#define GSTAGEB (2 * GTILEB)             // 69632
#define GSMEM (3 * GSTAGEB)              // 208896
#define GNCH 24                          // 3 terms x 8 k128-chunks

template<int EP>
__global__ __launch_bounds__(256, 1)
void tc_gemm(const __nv_bfloat16* __restrict__ A2,
             const __nv_bfloat16* __restrict__ W2q,
             const __nv_bfloat16* __restrict__ W2k,
             const __nv_bfloat16* __restrict__ W2v,
             void* __restrict__ O0, void* __restrict__ O1, void* __restrict__ O2) {
    extern __shared__ __align__(128) char smbuf[];
    const uint32_t sbase = smem_u32(smbuf);

    const __nv_bfloat16* W2 = (blockIdx.z == 0) ? W2q : (blockIdx.z == 1) ? W2k : W2v;
    void* OUT = (blockIdx.z == 0) ? O0 : (blockIdx.z == 1) ? O1 : O2;

    const int tid = threadIdx.x;
    const int wid = tid >> 5;
    const int lane = tid & 31;
    const int m0 = blockIdx.y * 128;
    const int n0 = blockIdx.x * 128;

    // loaders: r = tid>>1 (row 0..127), h = tid&1 (which 64-col half); 8 cp16 per matrix
    const int lr = tid >> 1;
    const int lh = tid & 1;
    const __nv_bfloat16* gA = A2 + (size_t)(m0 + lr) * 2048 + lh * 64;
    const __nv_bfloat16* gB = W2 + (size_t)(n0 + lr) * 2048 + lh * 64;
    const uint32_t sdA0 = sbase + lr * GROWB + lh * 128;
    const uint32_t sdB0 = sbase + GTILEB + lr * GROWB + lh * 128;
    const int offA[3] = { 0, 0, 1024 };
    const int offB[3] = { 0, 1024, 0 };

    const int mi = lane >> 3, rr = lane & 7;
    const int lmrow = (mi & 1) * 8 + rr;
    const int lmunit = (mi >> 1);
    const int wm = wid >> 1;             // 0..3 -> m = wm*32
    const int wn = wid & 1;              // 0..1 -> n = wn*64

    float acc[2][8][4];
#pragma unroll
    for (int am = 0; am < 2; am++)
#pragma unroll
        for (int bn = 0; bn < 8; bn++)
#pragma unroll
            for (int j = 0; j < 4; j++) acc[am][bn][j] = 0.f;

    // prologue: chunks 0,1 (term 0) -> stages 0,1
#pragma unroll
    for (int p = 0; p < 2; p++) {
        const __nv_bfloat16* sA = gA + offA[0] + p * 128;
        const __nv_bfloat16* sB = gB + offB[0] + p * 128;
        const uint32_t dA = sdA0 + p * GSTAGEB;
        const uint32_t dB = sdB0 + p * GSTAGEB;
#pragma unroll
        for (int q = 0; q < 8; q++) cp16(dA + q * 16, sA + q * 8);
#pragma unroll
        for (int q = 0; q < 8; q++) cp16(dB + q * 16, sB + q * 8);
        cp_commit();
    }

    for (int c = 0; c < GNCH; ++c) {
        if (c + 1 < GNCH) cp_wait<1>(); else cp_wait<0>();
        __syncthreads();

        if (c + 2 < GNCH) {
            const int cn = c + 2;
            const int t = cn >> 3, kc = cn & 7;
            const __nv_bfloat16* sA = gA + offA[t] + kc * 128;
            const __nv_bfloat16* sB = gB + offB[t] + kc * 128;
            const uint32_t dA = sdA0 + (uint32_t)(cn % 3) * GSTAGEB;
            const uint32_t dB = sdB0 + (uint32_t)(cn % 3) * GSTAGEB;
#pragma unroll
            for (int q = 0; q < 8; q++) cp16(dA + q * 16, sA + q * 8);
#pragma unroll
            for (int q = 0; q < 8; q++) cp16(dB + q * 16, sB + q * 8);
            cp_commit();
        }

        const uint32_t sA = sbase + (uint32_t)(c % 3) * GSTAGEB;
        const uint32_t sB = sA + GTILEB;
#pragma unroll
        for (int kb = 0; kb < 8; kb++) {
            uint32_t a[2][4];
#pragma unroll
            for (int am = 0; am < 2; am++)
                ldmat4(a[am][0], a[am][1], a[am][2], a[am][3],
                       sA + (wm * 32 + am * 16 + lmrow) * GROWB + (kb * 2 + lmunit) * 16);
#pragma unroll
            for (int bb = 0; bb < 4; bb++) {
                uint32_t r0, r1, r2, r3;
                ldmat4(r0, r1, r2, r3,
                       sB + (wn * 64 + bb * 16 + lmrow) * GROWB + (kb * 2 + lmunit) * 16);
#pragma unroll
                for (int am = 0; am < 2; am++) {
                    mma16816(acc[am][bb * 2],     a[am][0], a[am][1], a[am][2], a[am][3], r0, r2);
                    mma16816(acc[am][bb * 2 + 1], a[am][0], a[am][1], a[am][2], a[am][3], r1, r3);
                }
            }
        }
    }

    const int g = lane >> 2, it = lane & 3;
#pragma unroll
    for (int am = 0; am < 2; am++) {
        const int row0 = m0 + wm * 32 + am * 16 + g;
#pragma unroll
        for (int bn = 0; bn < 8; bn++) {
            const int col = n0 + wn * 64 + bn * 8 + it * 2;
            if (EP == 0) {
                float* p0 = (float*)OUT + (size_t)row0 * 1024 + col;
                float* p1 = p0 + 8 * 1024;
                *(float2*)p0 = make_float2(acc[am][bn][0], acc[am][bn][1]);
                *(float2*)p1 = make_float2(acc[am][bn][2], acc[am][bn][3]);
            } else {
                const int h = col >> 6, d = col & 63;
#pragma unroll
                for (int half = 0; half < 2; half++) {
                    float v0 = acc[am][bn][half * 2], v1 = acc[am][bn][half * 2 + 1];
                    __nv_bfloat16 h0 = __float2bfloat16_rn(v0);
                    __nv_bfloat16 h1 = __float2bfloat16_rn(v1);
                    __nv_bfloat162 hi2; hi2.x = h0; hi2.y = h1;
                    __nv_bfloat162 lo2;
                    lo2.x = __float2bfloat16_rn(v0 - __bfloat162float(h0));
                    lo2.y = __float2bfloat16_rn(v1 - __bfloat162float(h1));
                    __nv_bfloat16* op = (__nv_bfloat16*)OUT
                        + (size_t)(row0 + half * 8) * 2048 + h * 128 + d;
                    *(__nv_bfloat162*)op = hi2;
                    *(__nv_bfloat162*)(op + 64) = lo2;
                }
            }
        }
    }
}

// ================= HMMA flash attention (split bf16, 64-row K/V subtiles, occ 2) ======
#define TROW 272
#define QSZ (128 * TROW)                 // 34816
#define KVSUB (64 * TROW)                // 17408
#define ATTN_SMEM (QSZ + 4 * KVSUB)      // 104448

__global__ __launch_bounds__(256, 2)
void attn_tc(const float* __restrict__ mask,
             const __nv_bfloat16* __restrict__ Q2,
             const __nv_bfloat16* __restrict__ K2,
             const __nv_bfloat16* __restrict__ V2,
             __nv_bfloat16* __restrict__ Aout) {
    extern __shared__ __align__(128) char smc[];
    const uint32_t sq = smem_u32(smc);

    const int tid = threadIdx.x;
    const int wid = tid >> 5;
    const int lane = tid & 31;
    const int g = lane >> 2, it = lane & 3;
    const int lmrow = ((lane >> 3) & 1) * 8 + (lane & 7);
    const int lmunit = lane >> 4;

    const int b = blockIdx.z, h = blockIdx.y;
    const int q0 = blockIdx.x * 128;
    const size_t brow = (size_t)b * SS;

#pragma unroll
    for (int i = 0; i < 8; i++) {
        int idx = tid + i * 256;
        int u = idx & 15, r = idx >> 4;
        cp16(sq + r * TROW + u * 16, Q2 + (brow + q0 + r) * 2048 + h * 128 + u * 8);
    }
    cp_commit();

#pragma unroll
    for (int i = 0; i < 4; i++) {
        int idx = tid + i * 256;
        int u = idx & 15, r = idx >> 4;
        cp16(sq + QSZ + r * TROW + u * 16, K2 + (brow + r) * 2048 + h * 128 + u * 8);
        cp16(sq + QSZ + KVSUB + r * TROW + u * 16, V2 + (brow + r) * 2048 + h * 128 + u * 8);
    }
    cp_commit();

    float o[8][4];
#pragma unroll
    for (int dn = 0; dn < 8; dn++)
#pragma unroll
        for (int j = 0; j < 4; j++) o[dn][j] = 0.f;
    float mst0 = -INFINITY, mst1 = -INFINITY, l0 = 0.f, l1 = 0.f;

    const float* mrow0 = mask + ((size_t)b * SS + q0 + wid * 16 + g) * SS;
    const float* mrow1 = mrow0 + 8 * SS;

    uint32_t qh[4][4];
    bool qh_loaded = false;

    for (int st = 0; st < 32; st++) {
        const int cur = st & 1;
        cp_wait<0>();
        __syncthreads();

        if (st + 1 < 32) {
            const uint32_t kb = sq + QSZ + (uint32_t)(cur ^ 1) * (2 * KVSUB);
#pragma unroll
            for (int i = 0; i < 4; i++) {
                int idx = tid + i * 256;
                int u = idx & 15, r = idx >> 4;
                const size_t grow = brow + (size_t)(st + 1) * 64 + r;
                cp16(kb + r * TROW + u * 16, K2 + grow * 2048 + h * 128 + u * 8);
                cp16(kb + KVSUB + r * TROW + u * 16, V2 + grow * 2048 + h * 128 + u * 8);
            }
            cp_commit();
        }

        if (!qh_loaded) {
            qh_loaded = true;
#pragma unroll
            for (int u4 = 0; u4 < 4; u4++)
                ldmat4(qh[u4][0], qh[u4][1], qh[u4][2], qh[u4][3],
                       sq + (wid * 16 + lmrow) * TROW + (u4 * 2 + lmunit) * 16);
        }

        const uint32_t sk = sq + QSZ + (uint32_t)cur * (2 * KVSUB);
        const uint32_t sv = sk + KVSUB;

        float s[8][4];
#pragma unroll
        for (int nb = 0; nb < 8; nb++)
#pragma unroll
            for (int j = 0; j < 4; j++) s[nb][j] = 0.f;

#pragma unroll
        for (int u4 = 0; u4 < 4; u4++) {
            uint32_t ql0, ql1, ql2, ql3;
            ldmat4(ql0, ql1, ql2, ql3,
                   sq + (wid * 16 + lmrow) * TROW + (8 + u4 * 2 + lmunit) * 16);
#pragma unroll
            for (int nb16 = 0; nb16 < 4; nb16++) {
                uint32_t r0, r1, r2, r3;
                ldmat4(r0, r1, r2, r3,
                       sk + (nb16 * 16 + lmrow) * TROW + (u4 * 2 + lmunit) * 16);
                mma16816(s[nb16 * 2],     qh[u4][0], qh[u4][1], qh[u4][2], qh[u4][3], r0, r2);
                mma16816(s[nb16 * 2 + 1], qh[u4][0], qh[u4][1], qh[u4][2], qh[u4][3], r1, r3);
                mma16816(s[nb16 * 2],     ql0, ql1, ql2, ql3, r0, r2);
                mma16816(s[nb16 * 2 + 1], ql0, ql1, ql2, ql3, r1, r3);
            }
#pragma unroll
            for (int nb16 = 0; nb16 < 4; nb16++) {
                uint32_t r0, r1, r2, r3;
                ldmat4(r0, r1, r2, r3,
                       sk + (nb16 * 16 + lmrow) * TROW + (8 + u4 * 2 + lmunit) * 16);
                mma16816(s[nb16 * 2],     qh[u4][0], qh[u4][1], qh[u4][2], qh[u4][3], r0, r2);
                mma16816(s[nb16 * 2 + 1], qh[u4][0], qh[u4][1], qh[u4][2], qh[u4][3], r1, r3);
            }
        }

        float mx0 = -INFINITY, mx1 = -INFINITY;
#pragma unroll
        for (int nb = 0; nb < 8; nb++) {
            const int col = st * 64 + nb * 8 + it * 2;
            float2 m0 = *(const float2*)(mrow0 + col);
            float2 m1 = *(const float2*)(mrow1 + col);
            s[nb][0] = fmaf(s[nb][0], 0.125f, m0.x);
            s[nb][1] = fmaf(s[nb][1], 0.125f, m0.y);
            s[nb][2] = fmaf(s[nb][2], 0.125f, m1.x);
            s[nb][3] = fmaf(s[nb][3], 0.125f, m1.y);
            mx0 = fmaxf(mx0, fmaxf(s[nb][0], s[nb][1]));
            mx1 = fmaxf(mx1, fmaxf(s[nb][2], s[nb][3]));
        }
        mx0 = fmaxf(mx0, __shfl_xor_sync(0xffffffffu, mx0, 1));
        mx0 = fmaxf(mx0, __shfl_xor_sync(0xffffffffu, mx0, 2));
        mx1 = fmaxf(mx1, __shfl_xor_sync(0xffffffffu, mx1, 1));
        mx1 = fmaxf(mx1, __shfl_xor_sync(0xffffffffu, mx1, 2));

        const float nm0 = fmaxf(mst0, mx0), nm1 = fmaxf(mst1, mx1);
        const float corr0 = __expf(mst0 - nm0), corr1 = __expf(mst1 - nm1);
        mst0 = nm0; mst1 = nm1;

        uint32_t phi[16], plo[16];
        float sum0 = 0.f, sum1 = 0.f;
#pragma unroll
        for (int nb = 0; nb < 8; nb++) {
            float p0 = __expf(s[nb][0] - nm0);
            float p1 = __expf(s[nb][1] - nm0);
            float p2 = __expf(s[nb][2] - nm1);
            float p3 = __expf(s[nb][3] - nm1);
            sum0 += p0 + p1; sum1 += p2 + p3;
            float h0 = __bfloat162float(__float2bfloat16_rn(p0));
            float h1 = __bfloat162float(__float2bfloat16_rn(p1));
            float h2 = __bfloat162float(__float2bfloat16_rn(p2));
            float h3 = __bfloat162float(__float2bfloat16_rn(p3));
            const int u = nb >> 1;
            const int base = u * 4 + (nb & 1) * 2;
            phi[base]     = pack_bf2(h0, h1);
            phi[base + 1] = pack_bf2(h2, h3);
            plo[base]     = pack_bf2(p0 - h0, p1 - h1);
            plo[base + 1] = pack_bf2(p2 - h2, p3 - h3);
        }
        sum0 += __shfl_xor_sync(0xffffffffu, sum0, 1);
        sum0 += __shfl_xor_sync(0xffffffffu, sum0, 2);
        sum1 += __shfl_xor_sync(0xffffffffu, sum1, 1);
        sum1 += __shfl_xor_sync(0xffffffffu, sum1, 2);
        l0 = l0 * corr0 + sum0;
        l1 = l1 * corr1 + sum1;
#pragma unroll
        for (int dn = 0; dn < 8; dn++) {
            o[dn][0] *= corr0; o[dn][1] *= corr0;
            o[dn][2] *= corr1; o[dn][3] *= corr1;
        }

#pragma unroll
        for (int u = 0; u < 4; u++) {
            const uint32_t* ah = phi + u * 4;
            const uint32_t* al = plo + u * 4;
#pragma unroll
            for (int dn16 = 0; dn16 < 4; dn16++) {
                uint32_t r0, r1, r2, r3;
                ldmat4t(r0, r1, r2, r3,
                        sv + (u * 16 + lmrow) * TROW + (dn16 * 2 + lmunit) * 16);
                mma16816(o[dn16 * 2],     ah[0], ah[1], ah[2], ah[3], r0, r1);
                mma16816(o[dn16 * 2 + 1], ah[0], ah[1], ah[2], ah[3], r2, r3);
                mma16816(o[dn16 * 2],     al[0], al[1], al[2], al[3], r0, r1);
                mma16816(o[dn16 * 2 + 1], al[0], al[1], al[2], al[3], r2, r3);
            }
#pragma unroll
            for (int dn16 = 0; dn16 < 4; dn16++) {
                uint32_t r0, r1, r2, r3;
                ldmat4t(r0, r1, r2, r3,
                        sv + (u * 16 + lmrow) * TROW + (8 + dn16 * 2 + lmunit) * 16);
                mma16816(o[dn16 * 2],     ah[0], ah[1], ah[2], ah[3], r0, r1);
                mma16816(o[dn16 * 2 + 1], ah[0], ah[1], ah[2], ah[3], r2, r3);
            }
        }
    }

    const float inv0 = 1.f / l0, inv1 = 1.f / l1;
    const size_t row0 = brow + q0 + wid * 16 + g;
#pragma unroll
    for (int dn = 0; dn < 8; dn++) {
        const int col = h * 64 + dn * 8 + it * 2;
        float v0 = o[dn][0] * inv0, v1 = o[dn][1] * inv0;
        float v2 = o[dn][2] * inv1, v3 = o[dn][3] * inv1;
        __nv_bfloat16 h0 = __float2bfloat16_rn(v0), h1 = __float2bfloat16_rn(v1);
        __nv_bfloat16 h2 = __float2bfloat16_rn(v2), h3 = __float2bfloat16_rn(v3);
        __nv_bfloat162 hi01; hi01.x = h0; hi01.y = h1;
        __nv_bfloat162 hi23; hi23.x = h2; hi23.y = h3;
        __nv_bfloat162 lo01, lo23;
        lo01.x = __float2bfloat16_rn(v0 - __bfloat162float(h0));
        lo01.y = __float2bfloat16_rn(v1 - __bfloat162float(h1));
        lo23.x = __float2bfloat16_rn(v2 - __bfloat162float(h2));
        lo23.y = __float2bfloat16_rn(v3 - __bfloat162float(h3));
        __nv_bfloat16* p0 = Aout + row0 * 2048 + col;
        __nv_bfloat16* p1 = Aout + (row0 + 8) * 2048 + col;
        *(__nv_bfloat162*)p0 = hi01;
        *(__nv_bfloat162*)(p0 + 1024) = lo01;
        *(__nv_bfloat162*)p1 = hi23;
        *(__nv_bfloat162*)(p1 + 1024) = lo23;
    }
}

// ---------------- launch ----------------
extern "C" void kernel_launch(void* const* d_in, const int* in_sizes, int n_in,
                              void* d_out, int out_size) {
    (void)in_sizes; (void)n_in; (void)out_size;
    const float* hidden = (const float*)d_in[0];
    const float* mask   = (const float*)d_in[1];
    const float* qs = (const float*)d_in[2];
    const float* qd = (const float*)d_in[3];
    const float* ks = (const float*)d_in[4];
    const float* kd = (const float*)d_in[5];
    const float* vs = (const float*)d_in[6];
    const float* vd = (const float*)d_in[7];
    const float* os = (const float*)d_in[8];
    const float* od = (const float*)d_in[9];

    __nv_bfloat16 *a2, *wq2, *wk2, *wv2, *wo2, *q2, *k2, *v2;
    cudaGetSymbolAddress((void**)&a2,  g_a2);
    cudaGetSymbolAddress((void**)&wq2, g_wq2);
    cudaGetSymbolAddress((void**)&wk2, g_wk2);
    cudaGetSymbolAddress((void**)&wv2, g_wv2);
    cudaGetSymbolAddress((void**)&wo2, g_wo2);
    cudaGetSymbolAddress((void**)&q2,  g_q2);
    cudaGetSymbolAddress((void**)&k2,  g_k2);
    cudaGetSymbolAddress((void**)&v2,  g_v2);

    cudaFuncSetAttribute(tc_gemm<0>, cudaFuncAttributeMaxDynamicSharedMemorySize, GSMEM);
    cudaFuncSetAttribute(tc_gemm<1>, cudaFuncAttributeMaxDynamicSharedMemorySize, GSMEM);
    cudaFuncSetAttribute(attn_tc, cudaFuncAttributeMaxDynamicSharedMemorySize, ATTN_SMEM);

    // hi/lo splits
    split_kernel<<<MM, 256>>>(hidden, nullptr, a2);
    wsplit4_kernel<<<dim3(1024, 4), 256>>>(qs, qd, ks, kd, vs, vd, os, od,
                                           wq2, wk2, wv2, wo2);

    // Q,K,V projections -> per-head split bf16
    tc_gemm<1><<<dim3(8, 32, 3), 256, GSMEM>>>(a2, wq2, wk2, wv2, q2, k2, v2);

    // attention -> writes A2-format split directly into g_a2 (reused)
    attn_tc<<<dim3(SS / 128, NHH, BB), 256, ATTN_SMEM>>>(mask, q2, k2, v2, a2);

    // O projection -> fp32 d_out
    tc_gemm<0><<<dim3(8, 32, 1), 256, GSMEM>>>(a2, wo2, wo2, wo2,
                                               d_out, d_out, d_out);
}

// round 11
// speedup vs baseline: 1.0489x; 1.0489x over previous
#include <cuda_runtime.h>
#include <cuda_bf16.h>
#include <cstdint>

// Problem dims
#define BB  2
#define SS  2048
#define HH  1024
#define NHH 16
#define HDD 64
#define MM  (BB*SS)          // 4096 rows

// ---------------- scratch (no cudaMalloc allowed) ----------------
__device__ __nv_bfloat16 g_a2[MM * 2048];        // hi|lo split, [row][0:1024 hi | 1024:2048 lo]
__device__ __nv_bfloat16 g_wq2[HH * 2048];
__device__ __nv_bfloat16 g_wk2[HH * 2048];
__device__ __nv_bfloat16 g_wv2[HH * 2048];
__device__ __nv_bfloat16 g_wo2[HH * 2048];
// per-head split layout: [row][h*128 + (0:64 hi | 64:128 lo)]
__device__ __nv_bfloat16 g_q2[MM * 2048];
__device__ __nv_bfloat16 g_k2[MM * 2048];
__device__ __nv_bfloat16 g_v2[MM * 2048];

// ================= PTX helpers (non-'a' features only) =================
__device__ __forceinline__ uint32_t smem_u32(const void* p) {
    uint32_t a;
    asm("{ .reg .u64 t; cvta.to.shared.u64 t, %1; cvt.u32.u64 %0, t; }" : "=r"(a) : "l"(p));
    return a;
}
__device__ __forceinline__ void cp16(uint32_t dst, const void* src) {
    asm volatile("cp.async.cg.shared.global [%0], [%1], 16;" :: "r"(dst), "l"(src));
}
__device__ __forceinline__ void cp_commit() {
    asm volatile("cp.async.commit_group;" ::: "memory");
}
template<int N> __device__ __forceinline__ void cp_wait() {
    asm volatile("cp.async.wait_group %0;" :: "n"(N) : "memory");
}
__device__ __forceinline__ void ldmat4(uint32_t& r0, uint32_t& r1, uint32_t& r2, uint32_t& r3,
                                       uint32_t addr) {
    asm volatile("ldmatrix.sync.aligned.m8n8.x4.shared.b16 {%0,%1,%2,%3}, [%4];"
                 : "=r"(r0), "=r"(r1), "=r"(r2), "=r"(r3) : "r"(addr));
}
__device__ __forceinline__ void ldmat4t(uint32_t& r0, uint32_t& r1, uint32_t& r2, uint32_t& r3,
                                        uint32_t addr) {
    asm volatile("ldmatrix.sync.aligned.m8n8.x4.trans.shared.b16 {%0,%1,%2,%3}, [%4];"
                 : "=r"(r0), "=r"(r1), "=r"(r2), "=r"(r3) : "r"(addr));
}
__device__ __forceinline__ void mma16816(float* d, uint32_t a0, uint32_t a1, uint32_t a2,
                                         uint32_t a3, uint32_t b0, uint32_t b1) {
    asm volatile("mma.sync.aligned.m16n8k16.row.col.f32.bf16.bf16.f32 "
                 "{%0,%1,%2,%3},{%4,%5,%6,%7},{%8,%9},{%0,%1,%2,%3};"
                 : "+f"(d[0]), "+f"(d[1]), "+f"(d[2]), "+f"(d[3])
                 : "r"(a0), "r"(a1), "r"(a2), "r"(a3), "r"(b0), "r"(b1));
}
__device__ __forceinline__ uint32_t pack_bf2(float x, float y) {
    __nv_bfloat162 t;
    t.x = __float2bfloat16_rn(x);
    t.y = __float2bfloat16_rn(y);
    return *(uint32_t*)&t;
}

// ================= fused prep: hi/lo splits for activations + 4 weights ==============
__device__ __forceinline__ void do_split(const float* __restrict__ a,
                                         const float* __restrict__ b,
                                         __nv_bfloat16* __restrict__ out, int i) {
    int r = i >> 8;
    int c4 = (i & 255) << 2;
    float4 x = ((const float4*)a)[i];
    if (b) {
        float4 y = ((const float4*)b)[i];
        x.x += y.x; x.y += y.y; x.z += y.z; x.w += y.w;
    }
    float vf[4] = {x.x, x.y, x.z, x.w};
    __nv_bfloat16 h[4], l[4];
#pragma unroll
    for (int j = 0; j < 4; j++) {
        h[j] = __float2bfloat16_rn(vf[j]);
        l[j] = __float2bfloat16_rn(vf[j] - __bfloat162float(h[j]));
    }
    __nv_bfloat16* o = out + (size_t)r * 2048 + c4;
    ((__nv_bfloat162*)o)[0] = __halves2bfloat162(h[0], h[1]);
    ((__nv_bfloat162*)o)[1] = __halves2bfloat162(h[2], h[3]);
    ((__nv_bfloat162*)(o + 1024))[0] = __halves2bfloat162(l[0], l[1]);
    ((__nv_bfloat162*)(o + 1024))[1] = __halves2bfloat162(l[2], l[3]);
}

// grid (1024, 5): y=0..3 -> weights (1024x1024), y=4 -> activations (4096x1024, 4 iters)
__global__ void prep_kernel(const float* __restrict__ hid,
                            const float* __restrict__ s0, const float* __restrict__ d0,
                            const float* __restrict__ s1, const float* __restrict__ d1,
                            const float* __restrict__ s2, const float* __restrict__ d2,
                            const float* __restrict__ s3, const float* __restrict__ d3,
                            __nv_bfloat16* __restrict__ oa,
                            __nv_bfloat16* __restrict__ o0, __nv_bfloat16* __restrict__ o1,
                            __nv_bfloat16* __restrict__ o2, __nv_bfloat16* __restrict__ o3) {
    const int y = blockIdx.y;
    const int base = blockIdx.x * 256 + threadIdx.x;
    if (y == 4) {
#pragma unroll
        for (int k = 0; k < 4; k++)
            do_split(hid, nullptr, oa, base + k * 262144);
    } else {
        const float* a = (y == 0) ? s0 : (y == 1) ? s1 : (y == 2) ? s2 : s3;
        const float* b = (y == 0) ? d0 : (y == 1) ? d1 : (y == 2) ? d2 : d3;
        __nv_bfloat16* o = (y == 0) ? o0 : (y == 1) ? o1 : (y == 2) ? o2 : o3;
        do_split(a, b, o, base);
    }
}

// ================= HMMA split-bf16 GEMM (R6 config + warp skew) =================
// K-chunk 64, 3-stage cp.async, occ 2, 8 warps, warp tile 32x64.
// 144B padded rows (9 x 16B units; bijective mod 8 -> conflict-free).
// Warp skew: per-warp kb start (runtime) + bb order (template) de-phases the
// post-barrier LDSM storm.
#define GROWB 144
#define GTILEB (128 * GROWB)             // 18432
#define GSTAGEB (2 * GTILEB)             // 36864
#define GSMEM (3 * GSTAGEB)              // 110592
#define GNCH 48                          // 3 terms x 16 k64-chunks

template<int BBS>
__device__ __forceinline__ void gemm_chunk(uint32_t sA, uint32_t sB, int kbs,
                                           int wm, int wn, int lmrow, int lmunit,
                                           float acc[2][8][4]) {
#pragma unroll
    for (int kk = 0; kk < 4; kk++) {
        const int kb = (kk + kbs) & 3;
        uint32_t a[2][4];
#pragma unroll
        for (int am = 0; am < 2; am++)
            ldmat4(a[am][0], a[am][1], a[am][2], a[am][3],
                   sA + (wm * 32 + am * 16 + lmrow) * GROWB + (kb * 2 + lmunit) * 16);
#pragma unroll
        for (int bi = 0; bi < 4; bi++) {
            const int bb = (bi + BBS) & 3;            // compile-time per unrolled bi
            uint32_t r0, r1, r2, r3;
            ldmat4(r0, r1, r2, r3,
                   sB + (wn * 64 + bb * 16 + lmrow) * GROWB + (kb * 2 + lmunit) * 16);
#pragma unroll
            for (int am = 0; am < 2; am++) {
                mma16816(acc[am][bb * 2],     a[am][0], a[am][1], a[am][2], a[am][3], r0, r2);
                mma16816(acc[am][bb * 2 + 1], a[am][0], a[am][1], a[am][2], a[am][3], r1, r3);
            }
        }
    }
}

template<int EP>
__global__ __launch_bounds__(256, 2)
void tc_gemm(const __nv_bfloat16* __restrict__ A2,
             const __nv_bfloat16* __restrict__ W2q,
             const __nv_bfloat16* __restrict__ W2k,
             const __nv_bfloat16* __restrict__ W2v,
             void* __restrict__ O0, void* __restrict__ O1, void* __restrict__ O2) {
    extern __shared__ __align__(128) char smbuf[];
    const uint32_t sbase = smem_u32(smbuf);

    const __nv_bfloat16* W2 = (blockIdx.z == 0) ? W2q : (blockIdx.z == 1) ? W2k : W2v;
    void* OUT = (blockIdx.z == 0) ? O0 : (blockIdx.z == 1) ? O1 : O2;

    const int tid = threadIdx.x;
    const int wid = tid >> 5;
    const int lane = tid & 31;
    const int m0 = blockIdx.y * 128;
    const int n0 = blockIdx.x * 128;

    const int isA = (tid < 128);
    const int lrow128 = isA ? tid : (tid - 128);
    const __nv_bfloat16* gbase = isA ? (A2 + (size_t)(m0 + lrow128) * 2048)
                                     : (W2 + (size_t)(n0 + lrow128) * 2048);
    const uint32_t sdst0 = sbase + (isA ? 0 : GTILEB) + lrow128 * GROWB;
    const int offT[3] = { 0, isA ? 0 : 1024, isA ? 1024 : 0 };

    const int mi = lane >> 3, rr = lane & 7;
    const int lmrow = (mi & 1) * 8 + rr;
    const int lmunit = (mi >> 1);
    const int wm = wid >> 1;
    const int wn = wid & 1;
    // skew: both warps of one SMSP (wid, wid+4) and co-resident CTAs differ
    const int kbs = ((wid & 3) + ((wid >> 2) << 1) + (blockIdx.x & 1)) & 3;

    float acc[2][8][4];
#pragma unroll
    for (int am = 0; am < 2; am++)
#pragma unroll
        for (int bn = 0; bn < 8; bn++)
#pragma unroll
            for (int j = 0; j < 4; j++) acc[am][bn][j] = 0.f;

#pragma unroll
    for (int p = 0; p < 2; p++) {
        const __nv_bfloat16* src = gbase + offT[0] + p * 64;
        const uint32_t d = sdst0 + p * GSTAGEB;
#pragma unroll
        for (int q = 0; q < 8; q++) cp16(d + q * 16, src + q * 8);
        cp_commit();
    }

    for (int c = 0; c < GNCH; ++c) {
        if (c + 1 < GNCH) cp_wait<1>(); else cp_wait<0>();
        __syncthreads();

        if (c + 2 < GNCH) {
            const int cn = c + 2;
            const int t = cn >> 4, kc = cn & 15;
            const __nv_bfloat16* src = gbase + offT[t] + kc * 64;
            const uint32_t d = sdst0 + (uint32_t)(cn % 3) * GSTAGEB;
#pragma unroll
            for (int q = 0; q < 8; q++) cp16(d + q * 16, src + q * 8);
            cp_commit();
        }

        const uint32_t sA = sbase + (uint32_t)(c % 3) * GSTAGEB;
        const uint32_t sB = sA + GTILEB;
        if (wid < 4) gemm_chunk<0>(sA, sB, kbs, wm, wn, lmrow, lmunit, acc);
        else         gemm_chunk<2>(sA, sB, kbs, wm, wn, lmrow, lmunit, acc);
    }

    const int g = lane >> 2, it = lane & 3;
#pragma unroll
    for (int am = 0; am < 2; am++) {
        const int row0 = m0 + wm * 32 + am * 16 + g;
#pragma unroll
        for (int bn = 0; bn < 8; bn++) {
            const int col = n0 + wn * 64 + bn * 8 + it * 2;
            if (EP == 0) {
                float* p0 = (float*)OUT + (size_t)row0 * 1024 + col;
                float* p1 = p0 + 8 * 1024;
                *(float2*)p0 = make_float2(acc[am][bn][0], acc[am][bn][1]);
                *(float2*)p1 = make_float2(acc[am][bn][2], acc[am][bn][3]);
            } else {
                const int h = col >> 6, d = col & 63;
#pragma unroll
                for (int half = 0; half < 2; half++) {
                    float v0 = acc[am][bn][half * 2], v1 = acc[am][bn][half * 2 + 1];
                    __nv_bfloat16 h0 = __float2bfloat16_rn(v0);
                    __nv_bfloat16 h1 = __float2bfloat16_rn(v1);
                    __nv_bfloat162 hi2; hi2.x = h0; hi2.y = h1;
                    __nv_bfloat162 lo2;
                    lo2.x = __float2bfloat16_rn(v0 - __bfloat162float(h0));
                    lo2.y = __float2bfloat16_rn(v1 - __bfloat162float(h1));
                    __nv_bfloat16* op = (__nv_bfloat16*)OUT
                        + (size_t)(row0 + half * 8) * 2048 + h * 128 + d;
                    *(__nv_bfloat162*)op = hi2;
                    *(__nv_bfloat162*)(op + 64) = lo2;
                }
            }
        }
    }
}

// ================= HMMA flash attention (split bf16, 64-row K/V subtiles, occ 2) ======
#define TROW 272
#define QSZ (128 * TROW)                 // 34816
#define KVSUB (64 * TROW)                // 17408
#define ATTN_SMEM (QSZ + 4 * KVSUB)      // 104448

__global__ __launch_bounds__(256, 2)
void attn_tc(const float* __restrict__ mask,
             const __nv_bfloat16* __restrict__ Q2,
             const __nv_bfloat16* __restrict__ K2,
             const __nv_bfloat16* __restrict__ V2,
             __nv_bfloat16* __restrict__ Aout) {
    extern __shared__ __align__(128) char smc[];
    const uint32_t sq = smem_u32(smc);

    const int tid = threadIdx.x;
    const int wid = tid >> 5;
    const int lane = tid & 31;
    const int g = lane >> 2, it = lane & 3;
    const int lmrow = ((lane >> 3) & 1) * 8 + (lane & 7);
    const int lmunit = lane >> 4;

    const int b = blockIdx.z, h = blockIdx.y;
    const int q0 = blockIdx.x * 128;
    const size_t brow = (size_t)b * SS;

#pragma unroll
    for (int i = 0; i < 8; i++) {
        int idx = tid + i * 256;
        int u = idx & 15, r = idx >> 4;
        cp16(sq + r * TROW + u * 16, Q2 + (brow + q0 + r) * 2048 + h * 128 + u * 8);
    }
    cp_commit();

#pragma unroll
    for (int i = 0; i < 4; i++) {
        int idx = tid + i * 256;
        int u = idx & 15, r = idx >> 4;
        cp16(sq + QSZ + r * TROW + u * 16, K2 + (brow + r) * 2048 + h * 128 + u * 8);
        cp16(sq + QSZ + KVSUB + r * TROW + u * 16, V2 + (brow + r) * 2048 + h * 128 + u * 8);
    }
    cp_commit();

    float o[8][4];
#pragma unroll
    for (int dn = 0; dn < 8; dn++)
#pragma unroll
        for (int j = 0; j < 4; j++) o[dn][j] = 0.f;
    float mst0 = -INFINITY, mst1 = -INFINITY, l0 = 0.f, l1 = 0.f;

    const float* mrow0 = mask + ((size_t)b * SS + q0 + wid * 16 + g) * SS;
    const float* mrow1 = mrow0 + 8 * SS;

    uint32_t qh[4][4];
    bool qh_loaded = false;

    for (int st = 0; st < 32; st++) {
        const int cur = st & 1;
        cp_wait<0>();
        __syncthreads();

        if (st + 1 < 32) {
            const uint32_t kb = sq + QSZ + (uint32_t)(cur ^ 1) * (2 * KVSUB);
#pragma unroll
            for (int i = 0; i < 4; i++) {
                int idx = tid + i * 256;
                int u = idx & 15, r = idx >> 4;
                const size_t grow = brow + (size_t)(st + 1) * 64 + r;
                cp16(kb + r * TROW + u * 16, K2 + grow * 2048 + h * 128 + u * 8);
                cp16(kb + KVSUB + r * TROW + u * 16, V2 + grow * 2048 + h * 128 + u * 8);
            }
            cp_commit();
        }

        if (!qh_loaded) {
            qh_loaded = true;
#pragma unroll
            for (int u4 = 0; u4 < 4; u4++)
                ldmat4(qh[u4][0], qh[u4][1], qh[u4][2], qh[u4][3],
                       sq + (wid * 16 + lmrow) * TROW + (u4 * 2 + lmunit) * 16);
        }

        const uint32_t sk = sq + QSZ + (uint32_t)cur * (2 * KVSUB);
        const uint32_t sv = sk + KVSUB;

        float s[8][4];
#pragma unroll
        for (int nb = 0; nb < 8; nb++)
#pragma unroll
            for (int j = 0; j < 4; j++) s[nb][j] = 0.f;

#pragma unroll
        for (int u4 = 0; u4 < 4; u4++) {
            uint32_t ql0, ql1, ql2, ql3;
            ldmat4(ql0, ql1, ql2, ql3,
                   sq + (wid * 16 + lmrow) * TROW + (8 + u4 * 2 + lmunit) * 16);
#pragma unroll
            for (int nb16 = 0; nb16 < 4; nb16++) {
                uint32_t r0, r1, r2, r3;
                ldmat4(r0, r1, r2, r3,
                       sk + (nb16 * 16 + lmrow) * TROW + (u4 * 2 + lmunit) * 16);
                mma16816(s[nb16 * 2],     qh[u4][0], qh[u4][1], qh[u4][2], qh[u4][3], r0, r2);
                mma16816(s[nb16 * 2 + 1], qh[u4][0], qh[u4][1], qh[u4][2], qh[u4][3], r1, r3);
                mma16816(s[nb16 * 2],     ql0, ql1, ql2, ql3, r0, r2);
                mma16816(s[nb16 * 2 + 1], ql0, ql1, ql2, ql3, r1, r3);
            }
#pragma unroll
            for (int nb16 = 0; nb16 < 4; nb16++) {
                uint32_t r0, r1, r2, r3;
                ldmat4(r0, r1, r2, r3,
                       sk + (nb16 * 16 + lmrow) * TROW + (8 + u4 * 2 + lmunit) * 16);
                mma16816(s[nb16 * 2],     qh[u4][0], qh[u4][1], qh[u4][2], qh[u4][3], r0, r2);
                mma16816(s[nb16 * 2 + 1], qh[u4][0], qh[u4][1], qh[u4][2], qh[u4][3], r1, r3);
            }
        }

        float mx0 = -INFINITY, mx1 = -INFINITY;
#pragma unroll
        for (int nb = 0; nb < 8; nb++) {
            const int col = st * 64 + nb * 8 + it * 2;
            float2 m0 = *(const float2*)(mrow0 + col);
            float2 m1 = *(const float2*)(mrow1 + col);
            s[nb][0] = fmaf(s[nb][0], 0.125f, m0.x);
            s[nb][1] = fmaf(s[nb][1], 0.125f, m0.y);
            s[nb][2] = fmaf(s[nb][2], 0.125f, m1.x);
            s[nb][3] = fmaf(s[nb][3], 0.125f, m1.y);
            mx0 = fmaxf(mx0, fmaxf(s[nb][0], s[nb][1]));
            mx1 = fmaxf(mx1, fmaxf(s[nb][2], s[nb][3]));
        }
        mx0 = fmaxf(mx0, __shfl_xor_sync(0xffffffffu, mx0, 1));
        mx0 = fmaxf(mx0, __shfl_xor_sync(0xffffffffu, mx0, 2));
        mx1 = fmaxf(mx1, __shfl_xor_sync(0xffffffffu, mx1, 1));
        mx1 = fmaxf(mx1, __shfl_xor_sync(0xffffffffu, mx1, 2));

        const float nm0 = fmaxf(mst0, mx0), nm1 = fmaxf(mst1, mx1);
        const float corr0 = __expf(mst0 - nm0), corr1 = __expf(mst1 - nm1);
        mst0 = nm0; mst1 = nm1;

        uint32_t phi[16], plo[16];
        float sum0 = 0.f, sum1 = 0.f;
#pragma unroll
        for (int nb = 0; nb < 8; nb++) {
            float p0 = __expf(s[nb][0] - nm0);
            float p1 = __expf(s[nb][1] - nm0);
            float p2 = __expf(s[nb][2] - nm1);
            float p3 = __expf(s[nb][3] - nm1);
            sum0 += p0 + p1; sum1 += p2 + p3;
            float h0 = __bfloat162float(__float2bfloat16_rn(p0));
            float h1 = __bfloat162float(__float2bfloat16_rn(p1));
            float h2 = __bfloat162float(__float2bfloat16_rn(p2));
            float h3 = __bfloat162float(__float2bfloat16_rn(p3));
            const int u = nb >> 1;
            const int base = u * 4 + (nb & 1) * 2;
            phi[base]     = pack_bf2(h0, h1);
            phi[base + 1] = pack_bf2(h2, h3);
            plo[base]     = pack_bf2(p0 - h0, p1 - h1);
            plo[base + 1] = pack_bf2(p2 - h2, p3 - h3);
        }
        sum0 += __shfl_xor_sync(0xffffffffu, sum0, 1);
        sum0 += __shfl_xor_sync(0xffffffffu, sum0, 2);
        sum1 += __shfl_xor_sync(0xffffffffu, sum1, 1);
        sum1 += __shfl_xor_sync(0xffffffffu, sum1, 2);
        l0 = l0 * corr0 + sum0;
        l1 = l1 * corr1 + sum1;
#pragma unroll
        for (int dn = 0; dn < 8; dn++) {
            o[dn][0] *= corr0; o[dn][1] *= corr0;
            o[dn][2] *= corr1; o[dn][3] *= corr1;
        }

#pragma unroll
        for (int u = 0; u < 4; u++) {
            const uint32_t* ah = phi + u * 4;
            const uint32_t* al = plo + u * 4;
#pragma unroll
            for (int dn16 = 0; dn16 < 4; dn16++) {
                uint32_t r0, r1, r2, r3;
                ldmat4t(r0, r1, r2, r3,
                        sv + (u * 16 + lmrow) * TROW + (dn16 * 2 + lmunit) * 16);
                mma16816(o[dn16 * 2],     ah[0], ah[1], ah[2], ah[3], r0, r1);
                mma16816(o[dn16 * 2 + 1], ah[0], ah[1], ah[2], ah[3], r2, r3);
                mma16816(o[dn16 * 2],     al[0], al[1], al[2], al[3], r0, r1);
                mma16816(o[dn16 * 2 + 1], al[0], al[1], al[2], al[3], r2, r3);
            }
#pragma unroll
            for (int dn16 = 0; dn16 < 4; dn16++) {
                uint32_t r0, r1, r2, r3;
                ldmat4t(r0, r1, r2, r3,
                        sv + (u * 16 + lmrow) * TROW + (8 + dn16 * 2 + lmunit) * 16);
                mma16816(o[dn16 * 2],     ah[0], ah[1], ah[2], ah[3], r0, r1);
                mma16816(o[dn16 * 2 + 1], ah[0], ah[1], ah[2], ah[3], r2, r3);
            }
        }
    }

    const float inv0 = 1.f / l0, inv1 = 1.f / l1;
    const size_t row0 = brow + q0 + wid * 16 + g;
#pragma unroll
    for (int dn = 0; dn < 8; dn++) {
        const int col = h * 64 + dn * 8 + it * 2;
        float v0 = o[dn][0] * inv0, v1 = o[dn][1] * inv0;
        float v2 = o[dn][2] * inv1, v3 = o[dn][3] * inv1;
        __nv_bfloat16 h0 = __float2bfloat16_rn(v0), h1 = __float2bfloat16_rn(v1);
        __nv_bfloat16 h2 = __float2bfloat16_rn(v2), h3 = __float2bfloat16_rn(v3);
        __nv_bfloat162 hi01; hi01.x = h0; hi01.y = h1;
        __nv_bfloat162 hi23; hi23.x = h2; hi23.y = h3;
        __nv_bfloat162 lo01, lo23;
        lo01.x = __float2bfloat16_rn(v0 - __bfloat162float(h0));
        lo01.y = __float2bfloat16_rn(v1 - __bfloat162float(h1));
        lo23.x = __float2bfloat16_rn(v2 - __bfloat162float(h2));
        lo23.y = __float2bfloat16_rn(v3 - __bfloat162float(h3));
        __nv_bfloat16* p0 = Aout + row0 * 2048 + col;
        __nv_bfloat16* p1 = Aout + (row0 + 8) * 2048 + col;
        *(__nv_bfloat162*)p0 = hi01;
        *(__nv_bfloat162*)(p0 + 1024) = lo01;
        *(__nv_bfloat162*)p1 = hi23;
        *(__nv_bfloat162*)(p1 + 1024) = lo23;
    }
}

// ---------------- launch ----------------
extern "C" void kernel_launch(void* const* d_in, const int* in_sizes, int n_in,
                              void* d_out, int out_size) {
    (void)in_sizes; (void)n_in; (void)out_size;
    const float* hidden = (const float*)d_in[0];
    const float* mask   = (const float*)d_in[1];
    const float* qs = (const float*)d_in[2];
    const float* qd = (const float*)d_in[3];
    const float* ks = (const float*)d_in[4];
    const float* kd = (const float*)d_in[5];
    const float* vs = (const float*)d_in[6];
    const float* vd = (const float*)d_in[7];
    const float* os = (const float*)d_in[8];
    const float* od = (const float*)d_in[9];

    __nv_bfloat16 *a2, *wq2, *wk2, *wv2, *wo2, *q2, *k2, *v2;
    cudaGetSymbolAddress((void**)&a2,  g_a2);
    cudaGetSymbolAddress((void**)&wq2, g_wq2);
    cudaGetSymbolAddress((void**)&wk2, g_wk2);
    cudaGetSymbolAddress((void**)&wv2, g_wv2);
    cudaGetSymbolAddress((void**)&wo2, g_wo2);
    cudaGetSymbolAddress((void**)&q2,  g_q2);
    cudaGetSymbolAddress((void**)&k2,  g_k2);
    cudaGetSymbolAddress((void**)&v2,  g_v2);

    cudaFuncSetAttribute(tc_gemm<0>, cudaFuncAttributeMaxDynamicSharedMemorySize, GSMEM);
    cudaFuncSetAttribute(tc_gemm<1>, cudaFuncAttributeMaxDynamicSharedMemorySize, GSMEM);
    cudaFuncSetAttribute(attn_tc, cudaFuncAttributeMaxDynamicSharedMemorySize, ATTN_SMEM);

    // fused prep: activation + 4 weight hi/lo splits
    prep_kernel<<<dim3(1024, 5), 256>>>(hidden, qs, qd, ks, kd, vs, vd, os, od,
                                        a2, wq2, wk2, wv2, wo2);

    // Q,K,V projections -> per-head split bf16
    tc_gemm<1><<<dim3(8, 32, 3), 256, GSMEM>>>(a2, wq2, wk2, wv2, q2, k2, v2);

    // attention -> writes A2-format split directly into g_a2 (reused)
    attn_tc<<<dim3(SS / 128, NHH, BB), 256, ATTN_SMEM>>>(mask, q2, k2, v2, a2);

    // O projection -> fp32 d_out
    tc_gemm<0><<<dim3(8, 32, 1), 256, GSMEM>>>(a2, wo2, wo2, wo2,
                                               d_out, d_out, d_out);
}

// round 12
// speedup vs baseline: 1.2391x; 1.1813x over previous
#include <cuda_runtime.h>
#include <cuda_bf16.h>
#include <cstdint>

// Problem dims
#define BB  2
#define SS  2048
#define HH  1024
#define NHH 16
#define HDD 64
#define MM  (BB*SS)          // 4096 rows

// ---------------- scratch (no cudaMalloc allowed) ----------------
__device__ __nv_bfloat16 g_a2[MM * 2048];        // hi|lo split, [row][0:1024 hi | 1024:2048 lo]
__device__ __nv_bfloat16 g_wq2[HH * 2048];
__device__ __nv_bfloat16 g_wk2[HH * 2048];
__device__ __nv_bfloat16 g_wv2[HH * 2048];
__device__ __nv_bfloat16 g_wo2[HH * 2048];
// per-head split layout: [row][h*128 + (0:64 hi | 64:128 lo)]
__device__ __nv_bfloat16 g_q2[MM * 2048];
__device__ __nv_bfloat16 g_k2[MM * 2048];
__device__ __nv_bfloat16 g_v2[MM * 2048];

// ================= PTX helpers (non-'a' features only) =================
__device__ __forceinline__ uint32_t smem_u32(const void* p) {
    uint32_t a;
    asm("{ .reg .u64 t; cvta.to.shared.u64 t, %1; cvt.u32.u64 %0, t; }" : "=r"(a) : "l"(p));
    return a;
}
__device__ __forceinline__ void cp16(uint32_t dst, const void* src) {
    asm volatile("cp.async.cg.shared.global [%0], [%1], 16;" :: "r"(dst), "l"(src));
}
__device__ __forceinline__ void cp_commit() {
    asm volatile("cp.async.commit_group;" ::: "memory");
}
template<int N> __device__ __forceinline__ void cp_wait() {
    asm volatile("cp.async.wait_group %0;" :: "n"(N) : "memory");
}
__device__ __forceinline__ void ldmat4(uint32_t& r0, uint32_t& r1, uint32_t& r2, uint32_t& r3,
                                       uint32_t addr) {
    asm volatile("ldmatrix.sync.aligned.m8n8.x4.shared.b16 {%0,%1,%2,%3}, [%4];"
                 : "=r"(r0), "=r"(r1), "=r"(r2), "=r"(r3) : "r"(addr));
}
__device__ __forceinline__ void ldmat4t(uint32_t& r0, uint32_t& r1, uint32_t& r2, uint32_t& r3,
                                        uint32_t addr) {
    asm volatile("ldmatrix.sync.aligned.m8n8.x4.trans.shared.b16 {%0,%1,%2,%3}, [%4];"
                 : "=r"(r0), "=r"(r1), "=r"(r2), "=r"(r3) : "r"(addr));
}
__device__ __forceinline__ void mma16816(float* d, uint32_t a0, uint32_t a1, uint32_t a2,
                                         uint32_t a3, uint32_t b0, uint32_t b1) {
    asm volatile("mma.sync.aligned.m16n8k16.row.col.f32.bf16.bf16.f32 "
                 "{%0,%1,%2,%3},{%4,%5,%6,%7},{%8,%9},{%0,%1,%2,%3};"
                 : "+f"(d[0]), "+f"(d[1]), "+f"(d[2]), "+f"(d[3])
                 : "r"(a0), "r"(a1), "r"(a2), "r"(a3), "r"(b0), "r"(b1));
}
__device__ __forceinline__ uint32_t pack_bf2(float x, float y) {
    __nv_bfloat162 t;
    t.x = __float2bfloat16_rn(x);
    t.y = __float2bfloat16_rn(y);
    return *(uint32_t*)&t;
}

// ================= fused prep: hi/lo splits for activations + 4 weights ==============
__device__ __forceinline__ void do_split(const float* __restrict__ a,
                                         const float* __restrict__ b,
                                         __nv_bfloat16* __restrict__ out, int i) {
    int r = i >> 8;
    int c4 = (i & 255) << 2;
    float4 x = ((const float4*)a)[i];
    if (b) {
        float4 y = ((const float4*)b)[i];
        x.x += y.x; x.y += y.y; x.z += y.z; x.w += y.w;
    }
    float vf[4] = {x.x, x.y, x.z, x.w};
    __nv_bfloat16 h[4], l[4];
#pragma unroll
    for (int j = 0; j < 4; j++) {
        h[j] = __float2bfloat16_rn(vf[j]);
        l[j] = __float2bfloat16_rn(vf[j] - __bfloat162float(h[j]));
    }
    __nv_bfloat16* o = out + (size_t)r * 2048 + c4;
    ((__nv_bfloat162*)o)[0] = __halves2bfloat162(h[0], h[1]);
    ((__nv_bfloat162*)o)[1] = __halves2bfloat162(h[2], h[3]);
    ((__nv_bfloat162*)(o + 1024))[0] = __halves2bfloat162(l[0], l[1]);
    ((__nv_bfloat162*)(o + 1024))[1] = __halves2bfloat162(l[2], l[3]);
}

// grid (1024, 5): y=0..3 -> weights (1024x1024), y=4 -> activations (4096x1024, 4 iters)
__global__ void prep_kernel(const float* __restrict__ hid,
                            const float* __restrict__ s0, const float* __restrict__ d0,
                            const float* __restrict__ s1, const float* __restrict__ d1,
                            const float* __restrict__ s2, const float* __restrict__ d2,
                            const float* __restrict__ s3, const float* __restrict__ d3,
                            __nv_bfloat16* __restrict__ oa,
                            __nv_bfloat16* __restrict__ o0, __nv_bfloat16* __restrict__ o1,
                            __nv_bfloat16* __restrict__ o2, __nv_bfloat16* __restrict__ o3) {
    const int y = blockIdx.y;
    const int base = blockIdx.x * 256 + threadIdx.x;
    if (y == 4) {
#pragma unroll
        for (int k = 0; k < 4; k++)
            do_split(hid, nullptr, oa, base + k * 262144);
    } else {
        const float* a = (y == 0) ? s0 : (y == 1) ? s1 : (y == 2) ? s2 : s3;
        const float* b = (y == 0) ? d0 : (y == 1) ? d1 : (y == 2) ? d2 : d3;
        __nv_bfloat16* o = (y == 0) ? o0 : (y == 1) ? o1 : (y == 2) ? o2 : o3;
        do_split(a, b, o, base);
    }
}

// ================= HMMA split-bf16 GEMM (256x128 CTA tile, L2-traffic-reduced) ========
// 512 threads, 16 warps (4/SMSP), warp tile 64x32, K-chunk 64, 3-stage cp.async, occ 1.
// 144B padded rows (9 x 16B units; conflict-free for ldmatrix + 16B stores).
#define GROWB 144
#define GATILE (256 * GROWB)             // 36864 (A: 256 rows)
#define GBTILE (128 * GROWB)             // 18432 (B: 128 rows)
#define GSTAGEB (GATILE + GBTILE)        // 55296
#define GSMEM (3 * GSTAGEB)              // 165888
#define GNCH 48                          // 3 terms x 16 k64-chunks

template<int EP>
__global__ __launch_bounds__(512, 1)
void tc_gemm(const __nv_bfloat16* __restrict__ A2,
             const __nv_bfloat16* __restrict__ W2q,
             const __nv_bfloat16* __restrict__ W2k,
             const __nv_bfloat16* __restrict__ W2v,
             void* __restrict__ O0, void* __restrict__ O1, void* __restrict__ O2) {
    extern __shared__ __align__(128) char smbuf[];
    const uint32_t sbase = smem_u32(smbuf);

    const __nv_bfloat16* W2 = (blockIdx.z == 0) ? W2q : (blockIdx.z == 1) ? W2k : W2v;
    void* OUT = (blockIdx.z == 0) ? O0 : (blockIdx.z == 1) ? O1 : O2;

    const int tid = threadIdx.x;
    const int wid = tid >> 5;
    const int lane = tid & 31;
    const int m0 = blockIdx.y * 256;
    const int n0 = blockIdx.x * 128;

    // loaders: A: 2 threads/row (64B each, 4 cp16); B: 4 threads/row (32B each, 2 cp16)
    const int tAr = tid >> 1, tAh = tid & 1;
    const int tBr = tid >> 2, tBq = tid & 3;
    const __nv_bfloat16* gA = A2 + (size_t)(m0 + tAr) * 2048 + tAh * 32;
    const __nv_bfloat16* gB = W2 + (size_t)(n0 + tBr) * 2048 + tBq * 16;
    const uint32_t sdA0 = sbase + tAr * GROWB + tAh * 64;
    const uint32_t sdB0 = sbase + GATILE + tBr * GROWB + tBq * 32;
    const int offA[3] = { 0, 0, 1024 };
    const int offB[3] = { 0, 1024, 0 };

    const int mi = lane >> 3, rr = lane & 7;
    const int lmrow = (mi & 1) * 8 + rr;
    const int lmunit = (mi >> 1);
    const int wm = wid >> 2;             // 0..3 -> m = wm*64
    const int wn = wid & 3;              // 0..3 -> n = wn*32

    float acc[4][4][4];                  // [am 16-row][bn 8-col][frag]
#pragma unroll
    for (int am = 0; am < 4; am++)
#pragma unroll
        for (int bn = 0; bn < 4; bn++)
#pragma unroll
            for (int j = 0; j < 4; j++) acc[am][bn][j] = 0.f;

    // prologue: chunks 0,1 (term 0) -> stages 0,1
#pragma unroll
    for (int p = 0; p < 2; p++) {
        const __nv_bfloat16* sAg = gA + offA[0] + p * 64;
        const __nv_bfloat16* sBg = gB + offB[0] + p * 64;
        const uint32_t dA = sdA0 + p * GSTAGEB;
        const uint32_t dB = sdB0 + p * GSTAGEB;
#pragma unroll
        for (int q = 0; q < 4; q++) cp16(dA + q * 16, sAg + q * 8);
#pragma unroll
        for (int q = 0; q < 2; q++) cp16(dB + q * 16, sBg + q * 8);
        cp_commit();
    }

    for (int c = 0; c < GNCH; ++c) {
        if (c + 1 < GNCH) cp_wait<1>(); else cp_wait<0>();
        __syncthreads();

        if (c + 2 < GNCH) {
            const int cn = c + 2;
            const int t = cn >> 4, kc = cn & 15;
            const __nv_bfloat16* sAg = gA + offA[t] + kc * 64;
            const __nv_bfloat16* sBg = gB + offB[t] + kc * 64;
            const uint32_t dA = sdA0 + (uint32_t)(cn % 3) * GSTAGEB;
            const uint32_t dB = sdB0 + (uint32_t)(cn % 3) * GSTAGEB;
#pragma unroll
            for (int q = 0; q < 4; q++) cp16(dA + q * 16, sAg + q * 8);
#pragma unroll
            for (int q = 0; q < 2; q++) cp16(dB + q * 16, sBg + q * 8);
            cp_commit();
        }

        const uint32_t sA = sbase + (uint32_t)(c % 3) * GSTAGEB;
        const uint32_t sB = sA + GATILE;
#pragma unroll
        for (int kb = 0; kb < 4; kb++) {
            uint32_t a[4][4];
#pragma unroll
            for (int am = 0; am < 4; am++)
                ldmat4(a[am][0], a[am][1], a[am][2], a[am][3],
                       sA + (wm * 64 + am * 16 + lmrow) * GROWB + (kb * 2 + lmunit) * 16);
#pragma unroll
            for (int bb2 = 0; bb2 < 2; bb2++) {
                uint32_t r0, r1, r2, r3;
                ldmat4(r0, r1, r2, r3,
                       sB + (wn * 32 + bb2 * 16 + lmrow) * GROWB + (kb * 2 + lmunit) * 16);
#pragma unroll
                for (int am = 0; am < 4; am++) {
                    mma16816(acc[am][bb2 * 2],     a[am][0], a[am][1], a[am][2], a[am][3], r0, r2);
                    mma16816(acc[am][bb2 * 2 + 1], a[am][0], a[am][1], a[am][2], a[am][3], r1, r3);
                }
            }
        }
    }

    const int g = lane >> 2, it = lane & 3;
#pragma unroll
    for (int am = 0; am < 4; am++) {
        const int row0 = m0 + wm * 64 + am * 16 + g;
#pragma unroll
        for (int bn = 0; bn < 4; bn++) {
            const int col = n0 + wn * 32 + bn * 8 + it * 2;
            if (EP == 0) {
                float* p0 = (float*)OUT + (size_t)row0 * 1024 + col;
                float* p1 = p0 + 8 * 1024;
                *(float2*)p0 = make_float2(acc[am][bn][0], acc[am][bn][1]);
                *(float2*)p1 = make_float2(acc[am][bn][2], acc[am][bn][3]);
            } else {
                const int h = col >> 6, d = col & 63;
#pragma unroll
                for (int half = 0; half < 2; half++) {
                    float v0 = acc[am][bn][half * 2], v1 = acc[am][bn][half * 2 + 1];
                    __nv_bfloat16 h0 = __float2bfloat16_rn(v0);
                    __nv_bfloat16 h1 = __float2bfloat16_rn(v1);
                    __nv_bfloat162 hi2; hi2.x = h0; hi2.y = h1;
                    __nv_bfloat162 lo2;
                    lo2.x = __float2bfloat16_rn(v0 - __bfloat162float(h0));
                    lo2.y = __float2bfloat16_rn(v1 - __bfloat162float(h1));
                    __nv_bfloat16* op = (__nv_bfloat16*)OUT
                        + (size_t)(row0 + half * 8) * 2048 + h * 128 + d;
                    *(__nv_bfloat162*)op = hi2;
                    *(__nv_bfloat162*)(op + 64) = lo2;
                }
            }
        }
    }
}

// ================= HMMA flash attention (split bf16, 64-row K/V subtiles, occ 2) ======
#define TROW 272
#define QSZ (128 * TROW)                 // 34816
#define KVSUB (64 * TROW)                // 17408
#define ATTN_SMEM (QSZ + 4 * KVSUB)      // 104448

__global__ __launch_bounds__(256, 2)
void attn_tc(const float* __restrict__ mask,
             const __nv_bfloat16* __restrict__ Q2,
             const __nv_bfloat16* __restrict__ K2,
             const __nv_bfloat16* __restrict__ V2,
             __nv_bfloat16* __restrict__ Aout) {
    extern __shared__ __align__(128) char smc[];
    const uint32_t sq = smem_u32(smc);

    const int tid = threadIdx.x;
    const int wid = tid >> 5;
    const int lane = tid & 31;
    const int g = lane >> 2, it = lane & 3;
    const int lmrow = ((lane >> 3) & 1) * 8 + (lane & 7);
    const int lmunit = lane >> 4;

    const int b = blockIdx.z, h = blockIdx.y;
    const int q0 = blockIdx.x * 128;
    const size_t brow = (size_t)b * SS;

#pragma unroll
    for (int i = 0; i < 8; i++) {
        int idx = tid + i * 256;
        int u = idx & 15, r = idx >> 4;
        cp16(sq + r * TROW + u * 16, Q2 + (brow + q0 + r) * 2048 + h * 128 + u * 8);
    }
    cp_commit();

#pragma unroll
    for (int i = 0; i < 4; i++) {
        int idx = tid + i * 256;
        int u = idx & 15, r = idx >> 4;
        cp16(sq + QSZ + r * TROW + u * 16, K2 + (brow + r) * 2048 + h * 128 + u * 8);
        cp16(sq + QSZ + KVSUB + r * TROW + u * 16, V2 + (brow + r) * 2048 + h * 128 + u * 8);
    }
    cp_commit();

    float o[8][4];
#pragma unroll
    for (int dn = 0; dn < 8; dn++)
#pragma unroll
        for (int j = 0; j < 4; j++) o[dn][j] = 0.f;
    float mst0 = -INFINITY, mst1 = -INFINITY, l0 = 0.f, l1 = 0.f;

    const float* mrow0 = mask + ((size_t)b * SS + q0 + wid * 16 + g) * SS;
    const float* mrow1 = mrow0 + 8 * SS;

    uint32_t qh[4][4];
    bool qh_loaded = false;

    for (int st = 0; st < 32; st++) {
        const int cur = st & 1;
        cp_wait<0>();
        __syncthreads();

        if (st + 1 < 32) {
            const uint32_t kb = sq + QSZ + (uint32_t)(cur ^ 1) * (2 * KVSUB);
#pragma unroll
            for (int i = 0; i < 4; i++) {
                int idx = tid + i * 256;
                int u = idx & 15, r = idx >> 4;
                const size_t grow = brow + (size_t)(st + 1) * 64 + r;
                cp16(kb + r * TROW + u * 16, K2 + grow * 2048 + h * 128 + u * 8);
                cp16(kb + KVSUB + r * TROW + u * 16, V2 + grow * 2048 + h * 128 + u * 8);
            }
            cp_commit();
        }

        if (!qh_loaded) {
            qh_loaded = true;
#pragma unroll
            for (int u4 = 0; u4 < 4; u4++)
                ldmat4(qh[u4][0], qh[u4][1], qh[u4][2], qh[u4][3],
                       sq + (wid * 16 + lmrow) * TROW + (u4 * 2 + lmunit) * 16);
        }

        const uint32_t sk = sq + QSZ + (uint32_t)cur * (2 * KVSUB);
        const uint32_t sv = sk + KVSUB;

        float s[8][4];
#pragma unroll
        for (int nb = 0; nb < 8; nb++)
#pragma unroll
            for (int j = 0; j < 4; j++) s[nb][j] = 0.f;

#pragma unroll
        for (int u4 = 0; u4 < 4; u4++) {
            uint32_t ql0, ql1, ql2, ql3;
            ldmat4(ql0, ql1, ql2, ql3,
                   sq + (wid * 16 + lmrow) * TROW + (8 + u4 * 2 + lmunit) * 16);
#pragma unroll
            for (int nb16 = 0; nb16 < 4; nb16++) {
                uint32_t r0, r1, r2, r3;
                ldmat4(r0, r1, r2, r3,
                       sk + (nb16 * 16 + lmrow) * TROW + (u4 * 2 + lmunit) * 16);
                mma16816(s[nb16 * 2],     qh[u4][0], qh[u4][1], qh[u4][2], qh[u4][3], r0, r2);
                mma16816(s[nb16 * 2 + 1], qh[u4][0], qh[u4][1], qh[u4][2], qh[u4][3], r1, r3);
                mma16816(s[nb16 * 2],     ql0, ql1, ql2, ql3, r0, r2);
                mma16816(s[nb16 * 2 + 1], ql0, ql1, ql2, ql3, r1, r3);
            }
#pragma unroll
            for (int nb16 = 0; nb16 < 4; nb16++) {
                uint32_t r0, r1, r2, r3;
                ldmat4(r0, r1, r2, r3,
                       sk + (nb16 * 16 + lmrow) * TROW + (8 + u4 * 2 + lmunit) * 16);
                mma16816(s[nb16 * 2],     qh[u4][0], qh[u4][1], qh[u4][2], qh[u4][3], r0, r2);
                mma16816(s[nb16 * 2 + 1], qh[u4][0], qh[u4][1], qh[u4][2], qh[u4][3], r1, r3);
            }
        }

        float mx0 = -INFINITY, mx1 = -INFINITY;
#pragma unroll
        for (int nb = 0; nb < 8; nb++) {
            const int col = st * 64 + nb * 8 + it * 2;
            float2 m0 = *(const float2*)(mrow0 + col);
            float2 m1 = *(const float2*)(mrow1 + col);
            s[nb][0] = fmaf(s[nb][0], 0.125f, m0.x);
            s[nb][1] = fmaf(s[nb][1], 0.125f, m0.y);
            s[nb][2] = fmaf(s[nb][2], 0.125f, m1.x);
            s[nb][3] = fmaf(s[nb][3], 0.125f, m1.y);
            mx0 = fmaxf(mx0, fmaxf(s[nb][0], s[nb][1]));
            mx1 = fmaxf(mx1, fmaxf(s[nb][2], s[nb][3]));
        }
        mx0 = fmaxf(mx0, __shfl_xor_sync(0xffffffffu, mx0, 1));
        mx0 = fmaxf(mx0, __shfl_xor_sync(0xffffffffu, mx0, 2));
        mx1 = fmaxf(mx1, __shfl_xor_sync(0xffffffffu, mx1, 1));
        mx1 = fmaxf(mx1, __shfl_xor_sync(0xffffffffu, mx1, 2));

        const float nm0 = fmaxf(mst0, mx0), nm1 = fmaxf(mst1, mx1);
        const float corr0 = __expf(mst0 - nm0), corr1 = __expf(mst1 - nm1);
        mst0 = nm0; mst1 = nm1;

        uint32_t phi[16], plo[16];
        float sum0 = 0.f, sum1 = 0.f;
#pragma unroll
        for (int nb = 0; nb < 8; nb++) {
            float p0 = __expf(s[nb][0] - nm0);
            float p1 = __expf(s[nb][1] - nm0);
            float p2 = __expf(s[nb][2] - nm1);
            float p3 = __expf(s[nb][3] - nm1);
            sum0 += p0 + p1; sum1 += p2 + p3;
            float h0 = __bfloat162float(__float2bfloat16_rn(p0));
            float h1 = __bfloat162float(__float2bfloat16_rn(p1));
            float h2 = __bfloat162float(__float2bfloat16_rn(p2));
            float h3 = __bfloat162float(__float2bfloat16_rn(p3));
            const int u = nb >> 1;
            const int base = u * 4 + (nb & 1) * 2;
            phi[base]     = pack_bf2(h0, h1);
            phi[base + 1] = pack_bf2(h2, h3);
            plo[base]     = pack_bf2(p0 - h0, p1 - h1);
            plo[base + 1] = pack_bf2(p2 - h2, p3 - h3);
        }
        sum0 += __shfl_xor_sync(0xffffffffu, sum0, 1);
        sum0 += __shfl_xor_sync(0xffffffffu, sum0, 2);
        sum1 += __shfl_xor_sync(0xffffffffu, sum1, 1);
        sum1 += __shfl_xor_sync(0xffffffffu, sum1, 2);
        l0 = l0 * corr0 + sum0;
        l1 = l1 * corr1 + sum1;
#pragma unroll
        for (int dn = 0; dn < 8; dn++) {
            o[dn][0] *= corr0; o[dn][1] *= corr0;
            o[dn][2] *= corr1; o[dn][3] *= corr1;
        }

#pragma unroll
        for (int u = 0; u < 4; u++) {
            const uint32_t* ah = phi + u * 4;
            const uint32_t* al = plo + u * 4;
#pragma unroll
            for (int dn16 = 0; dn16 < 4; dn16++) {
                uint32_t r0, r1, r2, r3;
                ldmat4t(r0, r1, r2, r3,
                        sv + (u * 16 + lmrow) * TROW + (dn16 * 2 + lmunit) * 16);
                mma16816(o[dn16 * 2],     ah[0], ah[1], ah[2], ah[3], r0, r1);
                mma16816(o[dn16 * 2 + 1], ah[0], ah[1], ah[2], ah[3], r2, r3);
                mma16816(o[dn16 * 2],     al[0], al[1], al[2], al[3], r0, r1);
                mma16816(o[dn16 * 2 + 1], al[0], al[1], al[2], al[3], r2, r3);
            }
#pragma unroll
            for (int dn16 = 0; dn16 < 4; dn16++) {
                uint32_t r0, r1, r2, r3;
                ldmat4t(r0, r1, r2, r3,
                        sv + (u * 16 + lmrow) * TROW + (8 + dn16 * 2 + lmunit) * 16);
                mma16816(o[dn16 * 2],     ah[0], ah[1], ah[2], ah[3], r0, r1);
                mma16816(o[dn16 * 2 + 1], ah[0], ah[1], ah[2], ah[3], r2, r3);
            }
        }
    }

    const float inv0 = 1.f / l0, inv1 = 1.f / l1;
    const size_t row0 = brow + q0 + wid * 16 + g;
#pragma unroll
    for (int dn = 0; dn < 8; dn++) {
        const int col = h * 64 + dn * 8 + it * 2;
        float v0 = o[dn][0] * inv0, v1 = o[dn][1] * inv0;
        float v2 = o[dn][2] * inv1, v3 = o[dn][3] * inv1;
        __nv_bfloat16 h0 = __float2bfloat16_rn(v0), h1 = __float2bfloat16_rn(v1);
        __nv_bfloat16 h2 = __float2bfloat16_rn(v2), h3 = __float2bfloat16_rn(v3);
        __nv_bfloat162 hi01; hi01.x = h0; hi01.y = h1;
        __nv_bfloat162 hi23; hi23.x = h2; hi23.y = h3;
        __nv_bfloat162 lo01, lo23;
        lo01.x = __float2bfloat16_rn(v0 - __bfloat162float(h0));
        lo01.y = __float2bfloat16_rn(v1 - __bfloat162float(h1));
        lo23.x = __float2bfloat16_rn(v2 - __bfloat162float(h2));
        lo23.y = __float2bfloat16_rn(v3 - __bfloat162float(h3));
        __nv_bfloat16* p0 = Aout + row0 * 2048 + col;
        __nv_bfloat16* p1 = Aout + (row0 + 8) * 2048 + col;
        *(__nv_bfloat162*)p0 = hi01;
        *(__nv_bfloat162*)(p0 + 1024) = lo01;
        *(__nv_bfloat162*)p1 = hi23;
        *(__nv_bfloat162*)(p1 + 1024) = lo23;
    }
}

// ---------------- launch ----------------
extern "C" void kernel_launch(void* const* d_in, const int* in_sizes, int n_in,
                              void* d_out, int out_size) {
    (void)in_sizes; (void)n_in; (void)out_size;
    const float* hidden = (const float*)d_in[0];
    const float* mask   = (const float*)d_in[1];
    const float* qs = (const float*)d_in[2];
    const float* qd = (const float*)d_in[3];
    const float* ks = (const float*)d_in[4];
    const float* kd = (const float*)d_in[5];
    const float* vs = (const float*)d_in[6];
    const float* vd = (const float*)d_in[7];
    const float* os = (const float*)d_in[8];
    const float* od = (const float*)d_in[9];

    __nv_bfloat16 *a2, *wq2, *wk2, *wv2, *wo2, *q2, *k2, *v2;
    cudaGetSymbolAddress((void**)&a2,  g_a2);
    cudaGetSymbolAddress((void**)&wq2, g_wq2);
    cudaGetSymbolAddress((void**)&wk2, g_wk2);
    cudaGetSymbolAddress((void**)&wv2, g_wv2);
    cudaGetSymbolAddress((void**)&wo2, g_wo2);
    cudaGetSymbolAddress((void**)&q2,  g_q2);
    cudaGetSymbolAddress((void**)&k2,  g_k2);
    cudaGetSymbolAddress((void**)&v2,  g_v2);

    cudaFuncSetAttribute(tc_gemm<0>, cudaFuncAttributeMaxDynamicSharedMemorySize, GSMEM);
    cudaFuncSetAttribute(tc_gemm<1>, cudaFuncAttributeMaxDynamicSharedMemorySize, GSMEM);
    cudaFuncSetAttribute(attn_tc, cudaFuncAttributeMaxDynamicSharedMemorySize, ATTN_SMEM);

    // fused prep: activation + 4 weight hi/lo splits
    prep_kernel<<<dim3(1024, 5), 256>>>(hidden, qs, qd, ks, kd, vs, vd, os, od,
                                        a2, wq2, wk2, wv2, wo2);

    // Q,K,V projections -> per-head split bf16 (256x128 tiles: grid 8x16x3)
    tc_gemm<1><<<dim3(8, 16, 3), 512, GSMEM>>>(a2, wq2, wk2, wv2, q2, k2, v2);

    // attention -> writes A2-format split directly into g_a2 (reused)
    attn_tc<<<dim3(SS / 128, NHH, BB), 256, ATTN_SMEM>>>(mask, q2, k2, v2, a2);

    // O projection -> fp32 d_out (single wave: 128 CTAs)
    tc_gemm<0><<<dim3(8, 16, 1), 512, GSMEM>>>(a2, wo2, wo2, wo2,
                                               d_out, d_out, d_out);
}

// round 13
// speedup vs baseline: 1.3813x; 1.1147x over previous
#include <cuda_runtime.h>
#include <cuda_bf16.h>
#include <cuda_fp16.h>
#include <cstdint>

// Problem dims
#define BB  2
#define SS  2048
#define HH  1024
#define NHH 16
#define HDD 64
#define MM  (BB*SS)          // 4096 rows

// ---------------- scratch (no cudaMalloc allowed) ----------------
__device__ __nv_bfloat16 g_a2[MM * 2048];        // hi|lo split, [row][0:1024 hi | 1024:2048 lo]
__device__ __nv_bfloat16 g_wq2[HH * 2048];
__device__ __nv_bfloat16 g_wk2[HH * 2048];
__device__ __nv_bfloat16 g_wv2[HH * 2048];
__device__ __nv_bfloat16 g_wo2[HH * 2048];
// per-head split layout: [row][h*128 + (0:64 hi | 64:128 lo)]
__device__ __nv_bfloat16 g_q2[MM * 2048];
__device__ __nv_bfloat16 g_k2[MM * 2048];
// V: fp16 single, per-head layout [row][h*64 + d]
__device__ __half g_vh[MM * 1024];

// ================= PTX helpers (non-'a' features only) =================
__device__ __forceinline__ uint32_t smem_u32(const void* p) {
    uint32_t a;
    asm("{ .reg .u64 t; cvta.to.shared.u64 t, %1; cvt.u32.u64 %0, t; }" : "=r"(a) : "l"(p));
    return a;
}
__device__ __forceinline__ void cp16(uint32_t dst, const void* src) {
    asm volatile("cp.async.cg.shared.global [%0], [%1], 16;" :: "r"(dst), "l"(src));
}
__device__ __forceinline__ void cp_commit() {
    asm volatile("cp.async.commit_group;" ::: "memory");
}
template<int N> __device__ __forceinline__ void cp_wait() {
    asm volatile("cp.async.wait_group %0;" :: "n"(N) : "memory");
}
__device__ __forceinline__ void ldmat4(uint32_t& r0, uint32_t& r1, uint32_t& r2, uint32_t& r3,
                                       uint32_t addr) {
    asm volatile("ldmatrix.sync.aligned.m8n8.x4.shared.b16 {%0,%1,%2,%3}, [%4];"
                 : "=r"(r0), "=r"(r1), "=r"(r2), "=r"(r3) : "r"(addr));
}
__device__ __forceinline__ void ldmat4t(uint32_t& r0, uint32_t& r1, uint32_t& r2, uint32_t& r3,
                                        uint32_t addr) {
    asm volatile("ldmatrix.sync.aligned.m8n8.x4.trans.shared.b16 {%0,%1,%2,%3}, [%4];"
                 : "=r"(r0), "=r"(r1), "=r"(r2), "=r"(r3) : "r"(addr));
}
__device__ __forceinline__ void mma16816(float* d, uint32_t a0, uint32_t a1, uint32_t a2,
                                         uint32_t a3, uint32_t b0, uint32_t b1) {
    asm volatile("mma.sync.aligned.m16n8k16.row.col.f32.bf16.bf16.f32 "
                 "{%0,%1,%2,%3},{%4,%5,%6,%7},{%8,%9},{%0,%1,%2,%3};"
                 : "+f"(d[0]), "+f"(d[1]), "+f"(d[2]), "+f"(d[3])
                 : "r"(a0), "r"(a1), "r"(a2), "r"(a3), "r"(b0), "r"(b1));
}
__device__ __forceinline__ void mma16816h(float* d, uint32_t a0, uint32_t a1, uint32_t a2,
                                          uint32_t a3, uint32_t b0, uint32_t b1) {
    asm volatile("mma.sync.aligned.m16n8k16.row.col.f32.f16.f16.f32 "
                 "{%0,%1,%2,%3},{%4,%5,%6,%7},{%8,%9},{%0,%1,%2,%3};"
                 : "+f"(d[0]), "+f"(d[1]), "+f"(d[2]), "+f"(d[3])
                 : "r"(a0), "r"(a1), "r"(a2), "r"(a3), "r"(b0), "r"(b1));
}
__device__ __forceinline__ uint32_t pack_h2(float x, float y) {
    __half2 t = __floats2half2_rn(x, y);
    return *(uint32_t*)&t;
}

// ================= fused prep: hi/lo splits for activations + 4 weights ==============
__device__ __forceinline__ void do_split(const float* __restrict__ a,
                                         const float* __restrict__ b,
                                         __nv_bfloat16* __restrict__ out, int i) {
    int r = i >> 8;
    int c4 = (i & 255) << 2;
    float4 x = ((const float4*)a)[i];
    if (b) {
        float4 y = ((const float4*)b)[i];
        x.x += y.x; x.y += y.y; x.z += y.z; x.w += y.w;
    }
    float vf[4] = {x.x, x.y, x.z, x.w};
    __nv_bfloat16 h[4], l[4];
#pragma unroll
    for (int j = 0; j < 4; j++) {
        h[j] = __float2bfloat16_rn(vf[j]);
        l[j] = __float2bfloat16_rn(vf[j] - __bfloat162float(h[j]));
    }
    __nv_bfloat16* o = out + (size_t)r * 2048 + c4;
    ((__nv_bfloat162*)o)[0] = __halves2bfloat162(h[0], h[1]);
    ((__nv_bfloat162*)o)[1] = __halves2bfloat162(h[2], h[3]);
    ((__nv_bfloat162*)(o + 1024))[0] = __halves2bfloat162(l[0], l[1]);
    ((__nv_bfloat162*)(o + 1024))[1] = __halves2bfloat162(l[2], l[3]);
}

// grid (1024, 5): y=0..3 -> weights (1024x1024), y=4 -> activations (4096x1024, 4 iters)
__global__ void prep_kernel(const float* __restrict__ hid,
                            const float* __restrict__ s0, const float* __restrict__ d0,
                            const float* __restrict__ s1, const float* __restrict__ d1,
                            const float* __restrict__ s2, const float* __restrict__ d2,
                            const float* __restrict__ s3, const float* __restrict__ d3,
                            __nv_bfloat16* __restrict__ oa,
                            __nv_bfloat16* __restrict__ o0, __nv_bfloat16* __restrict__ o1,
                            __nv_bfloat16* __restrict__ o2, __nv_bfloat16* __restrict__ o3) {
    const int y = blockIdx.y;
    const int base = blockIdx.x * 256 + threadIdx.x;
    if (y == 4) {
#pragma unroll
        for (int k = 0; k < 4; k++)
            do_split(hid, nullptr, oa, base + k * 262144);
    } else {
        const float* a = (y == 0) ? s0 : (y == 1) ? s1 : (y == 2) ? s2 : s3;
        const float* b = (y == 0) ? d0 : (y == 1) ? d1 : (y == 2) ? d2 : d3;
        __nv_bfloat16* o = (y == 0) ? o0 : (y == 1) ? o1 : (y == 2) ? o2 : o3;
        do_split(a, b, o, base);
    }
}

// ================= HMMA split-bf16 GEMM (256x128 CTA tile, R12 config) ========
// 512 threads, 16 warps (4/SMSP), warp tile 64x32, K-chunk 64, 3-stage cp.async, occ 1.
#define GROWB 144
#define GATILE (256 * GROWB)             // 36864
#define GBTILE (128 * GROWB)             // 18432
#define GSTAGEB (GATILE + GBTILE)        // 55296
#define GSMEM (3 * GSTAGEB)              // 165888
#define GNCH 48                          // 3 terms x 16 k64-chunks

template<int EP>
__global__ __launch_bounds__(512, 1)
void tc_gemm(const __nv_bfloat16* __restrict__ A2,
             const __nv_bfloat16* __restrict__ W2q,
             const __nv_bfloat16* __restrict__ W2k,
             const __nv_bfloat16* __restrict__ W2v,
             void* __restrict__ O0, void* __restrict__ O1, void* __restrict__ O2) {
    extern __shared__ __align__(128) char smbuf[];
    const uint32_t sbase = smem_u32(smbuf);

    const __nv_bfloat16* W2 = (blockIdx.z == 0) ? W2q : (blockIdx.z == 1) ? W2k : W2v;
    void* OUT = (blockIdx.z == 0) ? O0 : (blockIdx.z == 1) ? O1 : O2;

    const int tid = threadIdx.x;
    const int wid = tid >> 5;
    const int lane = tid & 31;
    const int m0 = blockIdx.y * 256;
    const int n0 = blockIdx.x * 128;

    const int tAr = tid >> 1, tAh = tid & 1;
    const int tBr = tid >> 2, tBq = tid & 3;
    const __nv_bfloat16* gA = A2 + (size_t)(m0 + tAr) * 2048 + tAh * 32;
    const __nv_bfloat16* gB = W2 + (size_t)(n0 + tBr) * 2048 + tBq * 16;
    const uint32_t sdA0 = sbase + tAr * GROWB + tAh * 64;
    const uint32_t sdB0 = sbase + GATILE + tBr * GROWB + tBq * 32;
    const int offA[3] = { 0, 0, 1024 };
    const int offB[3] = { 0, 1024, 0 };

    const int mi = lane >> 3, rr = lane & 7;
    const int lmrow = (mi & 1) * 8 + rr;
    const int lmunit = (mi >> 1);
    const int wm = wid >> 2;
    const int wn = wid & 3;

    float acc[4][4][4];
#pragma unroll
    for (int am = 0; am < 4; am++)
#pragma unroll
        for (int bn = 0; bn < 4; bn++)
#pragma unroll
            for (int j = 0; j < 4; j++) acc[am][bn][j] = 0.f;

#pragma unroll
    for (int p = 0; p < 2; p++) {
        const __nv_bfloat16* sAg = gA + offA[0] + p * 64;
        const __nv_bfloat16* sBg = gB + offB[0] + p * 64;
        const uint32_t dA = sdA0 + p * GSTAGEB;
        const uint32_t dB = sdB0 + p * GSTAGEB;
#pragma unroll
        for (int q = 0; q < 4; q++) cp16(dA + q * 16, sAg + q * 8);
#pragma unroll
        for (int q = 0; q < 2; q++) cp16(dB + q * 16, sBg + q * 8);
        cp_commit();
    }

    for (int c = 0; c < GNCH; ++c) {
        if (c + 1 < GNCH) cp_wait<1>(); else cp_wait<0>();
        __syncthreads();

        if (c + 2 < GNCH) {
            const int cn = c + 2;
            const int t = cn >> 4, kc = cn & 15;
            const __nv_bfloat16* sAg = gA + offA[t] + kc * 64;
            const __nv_bfloat16* sBg = gB + offB[t] + kc * 64;
            const uint32_t dA = sdA0 + (uint32_t)(cn % 3) * GSTAGEB;
            const uint32_t dB = sdB0 + (uint32_t)(cn % 3) * GSTAGEB;
#pragma unroll
            for (int q = 0; q < 4; q++) cp16(dA + q * 16, sAg + q * 8);
#pragma unroll
            for (int q = 0; q < 2; q++) cp16(dB + q * 16, sBg + q * 8);
            cp_commit();
        }

        const uint32_t sA = sbase + (uint32_t)(c % 3) * GSTAGEB;
        const uint32_t sB = sA + GATILE;
#pragma unroll
        for (int kb = 0; kb < 4; kb++) {
            uint32_t a[4][4];
#pragma unroll
            for (int am = 0; am < 4; am++)
                ldmat4(a[am][0], a[am][1], a[am][2], a[am][3],
                       sA + (wm * 64 + am * 16 + lmrow) * GROWB + (kb * 2 + lmunit) * 16);
#pragma unroll
            for (int bb2 = 0; bb2 < 2; bb2++) {
                uint32_t r0, r1, r2, r3;
                ldmat4(r0, r1, r2, r3,
                       sB + (wn * 32 + bb2 * 16 + lmrow) * GROWB + (kb * 2 + lmunit) * 16);
#pragma unroll
                for (int am = 0; am < 4; am++) {
                    mma16816(acc[am][bb2 * 2],     a[am][0], a[am][1], a[am][2], a[am][3], r0, r2);
                    mma16816(acc[am][bb2 * 2 + 1], a[am][0], a[am][1], a[am][2], a[am][3], r1, r3);
                }
            }
        }
    }

    const int g = lane >> 2, it = lane & 3;
#pragma unroll
    for (int am = 0; am < 4; am++) {
        const int row0 = m0 + wm * 64 + am * 16 + g;
#pragma unroll
        for (int bn = 0; bn < 4; bn++) {
            const int col = n0 + wn * 32 + bn * 8 + it * 2;
            if (EP == 0) {
                float* p0 = (float*)OUT + (size_t)row0 * 1024 + col;
                float* p1 = p0 + 8 * 1024;
                *(float2*)p0 = make_float2(acc[am][bn][0], acc[am][bn][1]);
                *(float2*)p1 = make_float2(acc[am][bn][2], acc[am][bn][3]);
            } else if (blockIdx.z == 2) {
                // V: fp16 single, per-head [row][h*64+d]
                const int h = col >> 6, d = col & 63;
#pragma unroll
                for (int half_i = 0; half_i < 2; half_i++) {
                    __half2 hv = __floats2half2_rn(acc[am][bn][half_i * 2],
                                                   acc[am][bn][half_i * 2 + 1]);
                    __half* op = (__half*)OUT
                        + (size_t)(row0 + half_i * 8) * 1024 + h * 64 + d;
                    *(__half2*)op = hv;
                }
            } else {
                const int h = col >> 6, d = col & 63;
#pragma unroll
                for (int half_i = 0; half_i < 2; half_i++) {
                    float v0 = acc[am][bn][half_i * 2], v1 = acc[am][bn][half_i * 2 + 1];
                    __nv_bfloat16 h0 = __float2bfloat16_rn(v0);
                    __nv_bfloat16 h1 = __float2bfloat16_rn(v1);
                    __nv_bfloat162 hi2; hi2.x = h0; hi2.y = h1;
                    __nv_bfloat162 lo2;
                    lo2.x = __float2bfloat16_rn(v0 - __bfloat162float(h0));
                    lo2.y = __float2bfloat16_rn(v1 - __bfloat162float(h1));
                    __nv_bfloat16* op = (__nv_bfloat16*)OUT
                        + (size_t)(row0 + half_i * 8) * 2048 + h * 128 + d;
                    *(__nv_bfloat162*)op = hi2;
                    *(__nv_bfloat162*)(op + 64) = lo2;
                }
            }
        }
    }
}

// ================= HMMA flash attention: bf16-split QK + fp16 single-term PV =========
#define TROW 272
#define QSZ (128 * TROW)                 // 34816
#define KVSUB (64 * TROW)                // 17408 (K: 64 rows x 256B split)
#define VROW 144
#define VSUB (64 * VROW)                 // 9216  (V: 64 rows x 128B fp16)
#define KVSTRIDE (KVSUB + VSUB)          // 26624
#define ATTN_SMEM (QSZ + 2 * KVSTRIDE)   // 88064

__global__ __launch_bounds__(256, 2)
void attn_tc(const float* __restrict__ mask,
             const __nv_bfloat16* __restrict__ Q2,
             const __nv_bfloat16* __restrict__ K2,
             const __half* __restrict__ Vh,
             __nv_bfloat16* __restrict__ Aout) {
    extern __shared__ __align__(128) char smc[];
    const uint32_t sq = smem_u32(smc);

    const int tid = threadIdx.x;
    const int wid = tid >> 5;
    const int lane = tid & 31;
    const int g = lane >> 2, it = lane & 3;
    const int lmrow = ((lane >> 3) & 1) * 8 + (lane & 7);
    const int lmunit = lane >> 4;

    const int b = blockIdx.z, h = blockIdx.y;
    const int q0 = blockIdx.x * 128;
    const size_t brow = (size_t)b * SS;

    // Q tile
#pragma unroll
    for (int i = 0; i < 8; i++) {
        int idx = tid + i * 256;
        int u = idx & 15, r = idx >> 4;
        cp16(sq + r * TROW + u * 16, Q2 + (brow + q0 + r) * 2048 + h * 128 + u * 8);
    }
    cp_commit();

    // subtile 0: K (4 cp16/thr) + V (2 cp16/thr)
#pragma unroll
    for (int i = 0; i < 4; i++) {
        int idx = tid + i * 256;
        int u = idx & 15, r = idx >> 4;
        cp16(sq + QSZ + r * TROW + u * 16, K2 + (brow + r) * 2048 + h * 128 + u * 8);
    }
#pragma unroll
    for (int i = 0; i < 2; i++) {
        int idx = tid + i * 256;
        int u = idx & 7, r = idx >> 3;
        cp16(sq + QSZ + KVSUB + r * VROW + u * 16, Vh + (brow + r) * 1024 + h * 64 + u * 8);
    }
    cp_commit();

    float o[8][4];
#pragma unroll
    for (int dn = 0; dn < 8; dn++)
#pragma unroll
        for (int j = 0; j < 4; j++) o[dn][j] = 0.f;
    float mst0 = -INFINITY, mst1 = -INFINITY, l0 = 0.f, l1 = 0.f;

    const float* mrow0 = mask + ((size_t)b * SS + q0 + wid * 16 + g) * SS;
    const float* mrow1 = mrow0 + 8 * SS;

    uint32_t qh[4][4];
    bool qh_loaded = false;

    for (int st = 0; st < 32; st++) {
        const int cur = st & 1;
        cp_wait<0>();
        __syncthreads();

        if (st + 1 < 32) {
            const uint32_t kb = sq + QSZ + (uint32_t)(cur ^ 1) * KVSTRIDE;
            const size_t gbase = brow + (size_t)(st + 1) * 64;
#pragma unroll
            for (int i = 0; i < 4; i++) {
                int idx = tid + i * 256;
                int u = idx & 15, r = idx >> 4;
                cp16(kb + r * TROW + u * 16, K2 + (gbase + r) * 2048 + h * 128 + u * 8);
            }
#pragma unroll
            for (int i = 0; i < 2; i++) {
                int idx = tid + i * 256;
                int u = idx & 7, r = idx >> 3;
                cp16(kb + KVSUB + r * VROW + u * 16, Vh + (gbase + r) * 1024 + h * 64 + u * 8);
            }
            cp_commit();
        }

        if (!qh_loaded) {
            qh_loaded = true;
#pragma unroll
            for (int u4 = 0; u4 < 4; u4++)
                ldmat4(qh[u4][0], qh[u4][1], qh[u4][2], qh[u4][3],
                       sq + (wid * 16 + lmrow) * TROW + (u4 * 2 + lmunit) * 16);
        }

        const uint32_t sk = sq + QSZ + (uint32_t)cur * KVSTRIDE;
        const uint32_t sv = sk + KVSUB;

        // ---- S = 3-term QK^T (bf16 split) ----
        float s[8][4];
#pragma unroll
        for (int nb = 0; nb < 8; nb++)
#pragma unroll
            for (int j = 0; j < 4; j++) s[nb][j] = 0.f;

#pragma unroll
        for (int u4 = 0; u4 < 4; u4++) {
            uint32_t ql0, ql1, ql2, ql3;
            ldmat4(ql0, ql1, ql2, ql3,
                   sq + (wid * 16 + lmrow) * TROW + (8 + u4 * 2 + lmunit) * 16);
#pragma unroll
            for (int nb16 = 0; nb16 < 4; nb16++) {
                uint32_t r0, r1, r2, r3;
                ldmat4(r0, r1, r2, r3,
                       sk + (nb16 * 16 + lmrow) * TROW + (u4 * 2 + lmunit) * 16);
                mma16816(s[nb16 * 2],     qh[u4][0], qh[u4][1], qh[u4][2], qh[u4][3], r0, r2);
                mma16816(s[nb16 * 2 + 1], qh[u4][0], qh[u4][1], qh[u4][2], qh[u4][3], r1, r3);
                mma16816(s[nb16 * 2],     ql0, ql1, ql2, ql3, r0, r2);
                mma16816(s[nb16 * 2 + 1], ql0, ql1, ql2, ql3, r1, r3);
            }
#pragma unroll
            for (int nb16 = 0; nb16 < 4; nb16++) {
                uint32_t r0, r1, r2, r3;
                ldmat4(r0, r1, r2, r3,
                       sk + (nb16 * 16 + lmrow) * TROW + (8 + u4 * 2 + lmunit) * 16);
                mma16816(s[nb16 * 2],     qh[u4][0], qh[u4][1], qh[u4][2], qh[u4][3], r0, r2);
                mma16816(s[nb16 * 2 + 1], qh[u4][0], qh[u4][1], qh[u4][2], qh[u4][3], r1, r3);
            }
        }

        // ---- scale + mask + online softmax ----
        float mx0 = -INFINITY, mx1 = -INFINITY;
#pragma unroll
        for (int nb = 0; nb < 8; nb++) {
            const int col = st * 64 + nb * 8 + it * 2;
            float2 m0 = *(const float2*)(mrow0 + col);
            float2 m1 = *(const float2*)(mrow1 + col);
            s[nb][0] = fmaf(s[nb][0], 0.125f, m0.x);
            s[nb][1] = fmaf(s[nb][1], 0.125f, m0.y);
            s[nb][2] = fmaf(s[nb][2], 0.125f, m1.x);
            s[nb][3] = fmaf(s[nb][3], 0.125f, m1.y);
            mx0 = fmaxf(mx0, fmaxf(s[nb][0], s[nb][1]));
            mx1 = fmaxf(mx1, fmaxf(s[nb][2], s[nb][3]));
        }
        mx0 = fmaxf(mx0, __shfl_xor_sync(0xffffffffu, mx0, 1));
        mx0 = fmaxf(mx0, __shfl_xor_sync(0xffffffffu, mx0, 2));
        mx1 = fmaxf(mx1, __shfl_xor_sync(0xffffffffu, mx1, 1));
        mx1 = fmaxf(mx1, __shfl_xor_sync(0xffffffffu, mx1, 2));

        const float nm0 = fmaxf(mst0, mx0), nm1 = fmaxf(mst1, mx1);
        const float corr0 = __expf(mst0 - nm0), corr1 = __expf(mst1 - nm1);
        mst0 = nm0; mst1 = nm1;

        // exp + fp16 P fragments (single set)
        uint32_t ph[16];
        float sum0 = 0.f, sum1 = 0.f;
#pragma unroll
        for (int nb = 0; nb < 8; nb++) {
            float p0 = __expf(s[nb][0] - nm0);
            float p1 = __expf(s[nb][1] - nm0);
            float p2 = __expf(s[nb][2] - nm1);
            float p3 = __expf(s[nb][3] - nm1);
            sum0 += p0 + p1; sum1 += p2 + p3;
            const int u = nb >> 1;
            const int base = u * 4 + (nb & 1) * 2;
            ph[base]     = pack_h2(p0, p1);
            ph[base + 1] = pack_h2(p2, p3);
        }
        sum0 += __shfl_xor_sync(0xffffffffu, sum0, 1);
        sum0 += __shfl_xor_sync(0xffffffffu, sum0, 2);
        sum1 += __shfl_xor_sync(0xffffffffu, sum1, 1);
        sum1 += __shfl_xor_sync(0xffffffffu, sum1, 2);
        l0 = l0 * corr0 + sum0;
        l1 = l1 * corr1 + sum1;
#pragma unroll
        for (int dn = 0; dn < 8; dn++) {
            o[dn][0] *= corr0; o[dn][1] *= corr0;
            o[dn][2] *= corr1; o[dn][3] *= corr1;
        }

        // ---- O += P V, single-term fp16 ----
#pragma unroll
        for (int u = 0; u < 4; u++) {
            const uint32_t* ap = ph + u * 4;
#pragma unroll
            for (int dn16 = 0; dn16 < 4; dn16++) {
                uint32_t r0, r1, r2, r3;
                ldmat4t(r0, r1, r2, r3,
                        sv + (u * 16 + lmrow) * VROW + (dn16 * 2 + lmunit) * 16);
                mma16816h(o[dn16 * 2],     ap[0], ap[1], ap[2], ap[3], r0, r1);
                mma16816h(o[dn16 * 2 + 1], ap[0], ap[1], ap[2], ap[3], r2, r3);
            }
        }
    }

    // ---- epilogue: normalize, split hi/lo, write A2-format ----
    const float inv0 = 1.f / l0, inv1 = 1.f / l1;
    const size_t row0 = brow + q0 + wid * 16 + g;
#pragma unroll
    for (int dn = 0; dn < 8; dn++) {
        const int col = h * 64 + dn * 8 + it * 2;
        float v0 = o[dn][0] * inv0, v1 = o[dn][1] * inv0;
        float v2 = o[dn][2] * inv1, v3 = o[dn][3] * inv1;
        __nv_bfloat16 h0 = __float2bfloat16_rn(v0), h1 = __float2bfloat16_rn(v1);
        __nv_bfloat16 h2 = __float2bfloat16_rn(v2), h3 = __float2bfloat16_rn(v3);
        __nv_bfloat162 hi01; hi01.x = h0; hi01.y = h1;
        __nv_bfloat162 hi23; hi23.x = h2; hi23.y = h3;
        __nv_bfloat162 lo01, lo23;
        lo01.x = __float2bfloat16_rn(v0 - __bfloat162float(h0));
        lo01.y = __float2bfloat16_rn(v1 - __bfloat162float(h1));
        lo23.x = __float2bfloat16_rn(v2 - __bfloat162float(h2));
        lo23.y = __float2bfloat16_rn(v3 - __bfloat162float(h3));
        __nv_bfloat16* p0 = Aout + row0 * 2048 + col;
        __nv_bfloat16* p1 = Aout + (row0 + 8) * 2048 + col;
        *(__nv_bfloat162*)p0 = hi01;
        *(__nv_bfloat162*)(p0 + 1024) = lo01;
        *(__nv_bfloat162*)p1 = hi23;
        *(__nv_bfloat162*)(p1 + 1024) = lo23;
    }
}

// ---------------- launch ----------------
extern "C" void kernel_launch(void* const* d_in, const int* in_sizes, int n_in,
                              void* d_out, int out_size) {
    (void)in_sizes; (void)n_in; (void)out_size;
    const float* hidden = (const float*)d_in[0];
    const float* mask   = (const float*)d_in[1];
    const float* qs = (const float*)d_in[2];
    const float* qd = (const float*)d_in[3];
    const float* ks = (const float*)d_in[4];
    const float* kd = (const float*)d_in[5];
    const float* vs = (const float*)d_in[6];
    const float* vd = (const float*)d_in[7];
    const float* os = (const float*)d_in[8];
    const float* od = (const float*)d_in[9];

    __nv_bfloat16 *a2, *wq2, *wk2, *wv2, *wo2, *q2, *k2;
    __half *vh;
    cudaGetSymbolAddress((void**)&a2,  g_a2);
    cudaGetSymbolAddress((void**)&wq2, g_wq2);
    cudaGetSymbolAddress((void**)&wk2, g_wk2);
    cudaGetSymbolAddress((void**)&wv2, g_wv2);
    cudaGetSymbolAddress((void**)&wo2, g_wo2);
    cudaGetSymbolAddress((void**)&q2,  g_q2);
    cudaGetSymbolAddress((void**)&k2,  g_k2);
    cudaGetSymbolAddress((void**)&vh,  g_vh);

    cudaFuncSetAttribute(tc_gemm<0>, cudaFuncAttributeMaxDynamicSharedMemorySize, GSMEM);
    cudaFuncSetAttribute(tc_gemm<1>, cudaFuncAttributeMaxDynamicSharedMemorySize, GSMEM);
    cudaFuncSetAttribute(attn_tc, cudaFuncAttributeMaxDynamicSharedMemorySize, ATTN_SMEM);

    // fused prep: activation + 4 weight hi/lo splits
    prep_kernel<<<dim3(1024, 5), 256>>>(hidden, qs, qd, ks, kd, vs, vd, os, od,
                                        a2, wq2, wk2, wv2, wo2);

    // Q,K,V projections (V -> fp16 single)
    tc_gemm<1><<<dim3(8, 16, 3), 512, GSMEM>>>(a2, wq2, wk2, wv2, q2, k2, vh);

    // attention -> writes A2-format split directly into g_a2 (reused)
    attn_tc<<<dim3(SS / 128, NHH, BB), 256, ATTN_SMEM>>>(mask, q2, k2, vh, a2);

    // O projection -> fp32 d_out (single wave: 128 CTAs)
    tc_gemm<0><<<dim3(8, 16, 1), 512, GSMEM>>>(a2, wo2, wo2, wo2,
                                               d_out, d_out, d_out);
}

// round 14
// speedup vs baseline: 1.5223x; 1.1021x over previous
#include <cuda_runtime.h>
#include <cuda_bf16.h>
#include <cuda_fp16.h>
#include <cstdint>

// Problem dims
#define BB  2
#define SS  2048
#define HH  1024
#define NHH 16
#define HDD 64
#define MM  (BB*SS)          // 4096 rows

// ---------------- scratch (no cudaMalloc allowed) ----------------
__device__ __nv_bfloat16 g_a2[MM * 2048];        // bf16 hi|lo split activations (Q,K proj)
__device__ __half        g_ah[MM * 1024];        // fp16 single activations (V proj) / attn out (O proj)
__device__ __nv_bfloat16 g_wq2[HH * 2048];       // bf16 split
__device__ __nv_bfloat16 g_wk2[HH * 2048];
__device__ __half        g_wvh[HH * 2048];       // fp16 split [r][0:1024 hi | 1024:2048 lo]
__device__ __half        g_woh[HH * 2048];
// per-head split layout: [row][h*128 + (0:64 hi | 64:128 lo)]
__device__ __nv_bfloat16 g_q2[MM * 2048];
__device__ __nv_bfloat16 g_k2[MM * 2048];
// V: fp16 single, per-head layout [row][h*64 + d]
__device__ __half g_vh[MM * 1024];

// ================= PTX helpers (non-'a' features only) =================
__device__ __forceinline__ uint32_t smem_u32(const void* p) {
    uint32_t a;
    asm("{ .reg .u64 t; cvta.to.shared.u64 t, %1; cvt.u32.u64 %0, t; }" : "=r"(a) : "l"(p));
    return a;
}
__device__ __forceinline__ void cp16(uint32_t dst, const void* src) {
    asm volatile("cp.async.cg.shared.global [%0], [%1], 16;" :: "r"(dst), "l"(src));
}
__device__ __forceinline__ void cp_commit() {
    asm volatile("cp.async.commit_group;" ::: "memory");
}
template<int N> __device__ __forceinline__ void cp_wait() {
    asm volatile("cp.async.wait_group %0;" :: "n"(N) : "memory");
}
__device__ __forceinline__ void ldmat4(uint32_t& r0, uint32_t& r1, uint32_t& r2, uint32_t& r3,
                                       uint32_t addr) {
    asm volatile("ldmatrix.sync.aligned.m8n8.x4.shared.b16 {%0,%1,%2,%3}, [%4];"
                 : "=r"(r0), "=r"(r1), "=r"(r2), "=r"(r3) : "r"(addr));
}
__device__ __forceinline__ void ldmat4t(uint32_t& r0, uint32_t& r1, uint32_t& r2, uint32_t& r3,
                                        uint32_t addr) {
    asm volatile("ldmatrix.sync.aligned.m8n8.x4.trans.shared.b16 {%0,%1,%2,%3}, [%4];"
                 : "=r"(r0), "=r"(r1), "=r"(r2), "=r"(r3) : "r"(addr));
}
__device__ __forceinline__ void mma16816(float* d, uint32_t a0, uint32_t a1, uint32_t a2,
                                         uint32_t a3, uint32_t b0, uint32_t b1) {
    asm volatile("mma.sync.aligned.m16n8k16.row.col.f32.bf16.bf16.f32 "
                 "{%0,%1,%2,%3},{%4,%5,%6,%7},{%8,%9},{%0,%1,%2,%3};"
                 : "+f"(d[0]), "+f"(d[1]), "+f"(d[2]), "+f"(d[3])
                 : "r"(a0), "r"(a1), "r"(a2), "r"(a3), "r"(b0), "r"(b1));
}
__device__ __forceinline__ void mma16816h(float* d, uint32_t a0, uint32_t a1, uint32_t a2,
                                          uint32_t a3, uint32_t b0, uint32_t b1) {
    asm volatile("mma.sync.aligned.m16n8k16.row.col.f32.f16.f16.f32 "
                 "{%0,%1,%2,%3},{%4,%5,%6,%7},{%8,%9},{%0,%1,%2,%3};"
                 : "+f"(d[0]), "+f"(d[1]), "+f"(d[2]), "+f"(d[3])
                 : "r"(a0), "r"(a1), "r"(a2), "r"(a3), "r"(b0), "r"(b1));
}
__device__ __forceinline__ uint32_t pack_h2(float x, float y) {
    __half2 t = __floats2half2_rn(x, y);
    return *(uint32_t*)&t;
}

// ================= fused prep =================
__device__ __forceinline__ void split_bf(const float* __restrict__ a,
                                         const float* __restrict__ b,
                                         __nv_bfloat16* __restrict__ out, int i) {
    int r = i >> 8;
    int c4 = (i & 255) << 2;
    float4 x = ((const float4*)a)[i];
    if (b) {
        float4 y = ((const float4*)b)[i];
        x.x += y.x; x.y += y.y; x.z += y.z; x.w += y.w;
    }
    float vf[4] = {x.x, x.y, x.z, x.w};
    __nv_bfloat16 h[4], l[4];
#pragma unroll
    for (int j = 0; j < 4; j++) {
        h[j] = __float2bfloat16_rn(vf[j]);
        l[j] = __float2bfloat16_rn(vf[j] - __bfloat162float(h[j]));
    }
    __nv_bfloat16* o = out + (size_t)r * 2048 + c4;
    ((__nv_bfloat162*)o)[0] = __halves2bfloat162(h[0], h[1]);
    ((__nv_bfloat162*)o)[1] = __halves2bfloat162(h[2], h[3]);
    ((__nv_bfloat162*)(o + 1024))[0] = __halves2bfloat162(l[0], l[1]);
    ((__nv_bfloat162*)(o + 1024))[1] = __halves2bfloat162(l[2], l[3]);
}

__device__ __forceinline__ void split_h(const float* __restrict__ a,
                                        const float* __restrict__ b,
                                        __half* __restrict__ out, int i) {
    int r = i >> 8;
    int c4 = (i & 255) << 2;
    float4 x = ((const float4*)a)[i];
    float4 y = ((const float4*)b)[i];
    x.x += y.x; x.y += y.y; x.z += y.z; x.w += y.w;
    float vf[4] = {x.x, x.y, x.z, x.w};
    __half h[4], l[4];
#pragma unroll
    for (int j = 0; j < 4; j++) {
        h[j] = __float2half_rn(vf[j]);
        l[j] = __float2half_rn(vf[j] - __half2float(h[j]));
    }
    __half* o = out + (size_t)r * 2048 + c4;
    ((__half2*)o)[0] = __halves2half2(h[0], h[1]);
    ((__half2*)o)[1] = __halves2half2(h[2], h[3]);
    ((__half2*)(o + 1024))[0] = __halves2half2(l[0], l[1]);
    ((__half2*)(o + 1024))[1] = __halves2half2(l[2], l[3]);
}

// grid (1024, 5): y=0 wq(bf16) y=1 wk(bf16) y=2 wv(fp16) y=3 wo(fp16)
//                 y=4 activations -> bf16 split + fp16 single (4 iters)
__global__ void prep_kernel(const float* __restrict__ hid,
                            const float* __restrict__ s0, const float* __restrict__ d0,
                            const float* __restrict__ s1, const float* __restrict__ d1,
                            const float* __restrict__ s2, const float* __restrict__ d2,
                            const float* __restrict__ s3, const float* __restrict__ d3,
                            __nv_bfloat16* __restrict__ oa, __half* __restrict__ oah,
                            __nv_bfloat16* __restrict__ o0, __nv_bfloat16* __restrict__ o1,
                            __half* __restrict__ o2, __half* __restrict__ o3) {
    const int y = blockIdx.y;
    const int base = blockIdx.x * 256 + threadIdx.x;
    if (y == 4) {
#pragma unroll
        for (int k = 0; k < 4; k++) {
            const int i = base + k * 262144;
            split_bf(hid, nullptr, oa, i);
            float4 x = ((const float4*)hid)[i];
            int r = i >> 8, c4 = (i & 255) << 2;
            __half* o = oah + (size_t)r * 1024 + c4;
            ((__half2*)o)[0] = __floats2half2_rn(x.x, x.y);
            ((__half2*)o)[1] = __floats2half2_rn(x.z, x.w);
        }
    } else if (y == 0) split_bf(s0, d0, o0, base);
    else if (y == 1) split_bf(s1, d1, o1, base);
    else if (y == 2) split_h(s2, d2, o2, base);
    else             split_h(s3, d3, o3, base);
}

// ================= bf16 3-term GEMM (Q,K projections; 256x128 tiles) ========
#define GROWB 144
#define GATILE (256 * GROWB)             // 36864
#define GBTILE (128 * GROWB)             // 18432
#define GSTAGEB (GATILE + GBTILE)        // 55296
#define GSMEM (3 * GSTAGEB)              // 165888
#define GNCH 48                          // 3 terms x 16 k64-chunks

__global__ __launch_bounds__(512, 1)
void tc_gemm(const __nv_bfloat16* __restrict__ A2,
             const __nv_bfloat16* __restrict__ W2q,
             const __nv_bfloat16* __restrict__ W2k,
             __nv_bfloat16* __restrict__ O0, __nv_bfloat16* __restrict__ O1) {
    extern __shared__ __align__(128) char smbuf[];
    const uint32_t sbase = smem_u32(smbuf);

    const __nv_bfloat16* W2 = (blockIdx.z == 0) ? W2q : W2k;
    __nv_bfloat16* OUT = (blockIdx.z == 0) ? O0 : O1;

    const int tid = threadIdx.x;
    const int wid = tid >> 5;
    const int lane = tid & 31;
    const int m0 = blockIdx.y * 256;
    const int n0 = blockIdx.x * 128;

    const int tAr = tid >> 1, tAh = tid & 1;
    const int tBr = tid >> 2, tBq = tid & 3;
    const __nv_bfloat16* gA = A2 + (size_t)(m0 + tAr) * 2048 + tAh * 32;
    const __nv_bfloat16* gB = W2 + (size_t)(n0 + tBr) * 2048 + tBq * 16;
    const uint32_t sdA0 = sbase + tAr * GROWB + tAh * 64;
    const uint32_t sdB0 = sbase + GATILE + tBr * GROWB + tBq * 32;
    const int offA[3] = { 0, 0, 1024 };
    const int offB[3] = { 0, 1024, 0 };

    const int mi = lane >> 3, rr = lane & 7;
    const int lmrow = (mi & 1) * 8 + rr;
    const int lmunit = (mi >> 1);
    const int wm = wid >> 2;
    const int wn = wid & 3;

    float acc[4][4][4];
#pragma unroll
    for (int am = 0; am < 4; am++)
#pragma unroll
        for (int bn = 0; bn < 4; bn++)
#pragma unroll
            for (int j = 0; j < 4; j++) acc[am][bn][j] = 0.f;

#pragma unroll
    for (int p = 0; p < 2; p++) {
        const __nv_bfloat16* sAg = gA + offA[0] + p * 64;
        const __nv_bfloat16* sBg = gB + offB[0] + p * 64;
        const uint32_t dA = sdA0 + p * GSTAGEB;
        const uint32_t dB = sdB0 + p * GSTAGEB;
#pragma unroll
        for (int q = 0; q < 4; q++) cp16(dA + q * 16, sAg + q * 8);
#pragma unroll
        for (int q = 0; q < 2; q++) cp16(dB + q * 16, sBg + q * 8);
        cp_commit();
    }

    for (int c = 0; c < GNCH; ++c) {
        if (c + 1 < GNCH) cp_wait<1>(); else cp_wait<0>();
        __syncthreads();

        if (c + 2 < GNCH) {
            const int cn = c + 2;
            const int t = cn >> 4, kc = cn & 15;
            const __nv_bfloat16* sAg = gA + offA[t] + kc * 64;
            const __nv_bfloat16* sBg = gB + offB[t] + kc * 64;
            const uint32_t dA = sdA0 + (uint32_t)(cn % 3) * GSTAGEB;
            const uint32_t dB = sdB0 + (uint32_t)(cn % 3) * GSTAGEB;
#pragma unroll
            for (int q = 0; q < 4; q++) cp16(dA + q * 16, sAg + q * 8);
#pragma unroll
            for (int q = 0; q < 2; q++) cp16(dB + q * 16, sBg + q * 8);
            cp_commit();
        }

        const uint32_t sA = sbase + (uint32_t)(c % 3) * GSTAGEB;
        const uint32_t sB = sA + GATILE;
#pragma unroll
        for (int kb = 0; kb < 4; kb++) {
            uint32_t a[4][4];
#pragma unroll
            for (int am = 0; am < 4; am++)
                ldmat4(a[am][0], a[am][1], a[am][2], a[am][3],
                       sA + (wm * 64 + am * 16 + lmrow) * GROWB + (kb * 2 + lmunit) * 16);
#pragma unroll
            for (int bb2 = 0; bb2 < 2; bb2++) {
                uint32_t r0, r1, r2, r3;
                ldmat4(r0, r1, r2, r3,
                       sB + (wn * 32 + bb2 * 16 + lmrow) * GROWB + (kb * 2 + lmunit) * 16);
#pragma unroll
                for (int am = 0; am < 4; am++) {
                    mma16816(acc[am][bb2 * 2],     a[am][0], a[am][1], a[am][2], a[am][3], r0, r2);
                    mma16816(acc[am][bb2 * 2 + 1], a[am][0], a[am][1], a[am][2], a[am][3], r1, r3);
                }
            }
        }
    }

    const int g = lane >> 2, it = lane & 3;
#pragma unroll
    for (int am = 0; am < 4; am++) {
        const int row0 = m0 + wm * 64 + am * 16 + g;
#pragma unroll
        for (int bn = 0; bn < 4; bn++) {
            const int col = n0 + wn * 32 + bn * 8 + it * 2;
            const int h = col >> 6, d = col & 63;
#pragma unroll
            for (int half_i = 0; half_i < 2; half_i++) {
                float v0 = acc[am][bn][half_i * 2], v1 = acc[am][bn][half_i * 2 + 1];
                __nv_bfloat16 h0 = __float2bfloat16_rn(v0);
                __nv_bfloat16 h1 = __float2bfloat16_rn(v1);
                __nv_bfloat162 hi2; hi2.x = h0; hi2.y = h1;
                __nv_bfloat162 lo2;
                lo2.x = __float2bfloat16_rn(v0 - __bfloat162float(h0));
                lo2.y = __float2bfloat16_rn(v1 - __bfloat162float(h1));
                __nv_bfloat16* op = OUT + (size_t)(row0 + half_i * 8) * 2048 + h * 128 + d;
                *(__nv_bfloat162*)op = hi2;
                *(__nv_bfloat162*)(op + 64) = lo2;
            }
        }
    }
}

// ================= fp16 2-term GEMM (V and O projections) ========
// A fp16 single [4096][1024]; W fp16 split [1024][0:1024 hi | 1024:2048 lo]. K=2048.
#define HNCH 32                          // 2 terms x 16 k64-chunks

template<int EP>
__global__ __launch_bounds__(512, 1)
void tc_gemm_h(const __half* __restrict__ Ah,
               const __half* __restrict__ Wh,
               void* __restrict__ OUT) {
    extern __shared__ __align__(128) char smbuf[];
    const uint32_t sbase = smem_u32(smbuf);

    const int tid = threadIdx.x;
    const int wid = tid >> 5;
    const int lane = tid & 31;
    const int m0 = blockIdx.y * 256;
    const int n0 = blockIdx.x * 128;

    const int tAr = tid >> 1, tAh = tid & 1;
    const int tBr = tid >> 2, tBq = tid & 3;
    const __half* gA = Ah + (size_t)(m0 + tAr) * 1024 + tAh * 32;
    const __half* gB = Wh + (size_t)(n0 + tBr) * 2048 + tBq * 16;
    const uint32_t sdA0 = sbase + tAr * GROWB + tAh * 64;
    const uint32_t sdB0 = sbase + GATILE + tBr * GROWB + tBq * 32;

    const int mi = lane >> 3, rr = lane & 7;
    const int lmrow = (mi & 1) * 8 + rr;
    const int lmunit = (mi >> 1);
    const int wm = wid >> 2;
    const int wn = wid & 3;

    float acc[4][4][4];
#pragma unroll
    for (int am = 0; am < 4; am++)
#pragma unroll
        for (int bn = 0; bn < 4; bn++)
#pragma unroll
            for (int j = 0; j < 4; j++) acc[am][bn][j] = 0.f;

#pragma unroll
    for (int p = 0; p < 2; p++) {
        const __half* sAg = gA + p * 64;          // term 0, A offset = kc*64
        const __half* sBg = gB + p * 64;
        const uint32_t dA = sdA0 + p * GSTAGEB;
        const uint32_t dB = sdB0 + p * GSTAGEB;
#pragma unroll
        for (int q = 0; q < 4; q++) cp16(dA + q * 16, sAg + q * 8);
#pragma unroll
        for (int q = 0; q < 2; q++) cp16(dB + q * 16, sBg + q * 8);
        cp_commit();
    }

    for (int c = 0; c < HNCH; ++c) {
        if (c + 1 < HNCH) cp_wait<1>(); else cp_wait<0>();
        __syncthreads();

        if (c + 2 < HNCH) {
            const int cn = c + 2;
            const int t = cn >> 4, kc = cn & 15;     // t=0: Whi, t=1: Wlo; A same both
            const __half* sAg = gA + kc * 64;
            const __half* sBg = gB + t * 1024 + kc * 64;
            const uint32_t dA = sdA0 + (uint32_t)(cn % 3) * GSTAGEB;
            const uint32_t dB = sdB0 + (uint32_t)(cn % 3) * GSTAGEB;
#pragma unroll
            for (int q = 0; q < 4; q++) cp16(dA + q * 16, sAg + q * 8);
#pragma unroll
            for (int q = 0; q < 2; q++) cp16(dB + q * 16, sBg + q * 8);
            cp_commit();
        }

        const uint32_t sA = sbase + (uint32_t)(c % 3) * GSTAGEB;
        const uint32_t sB = sA + GATILE;
#pragma unroll
        for (int kb = 0; kb < 4; kb++) {
            uint32_t a[4][4];
#pragma unroll
            for (int am = 0; am < 4; am++)
                ldmat4(a[am][0], a[am][1], a[am][2], a[am][3],
                       sA + (wm * 64 + am * 16 + lmrow) * GROWB + (kb * 2 + lmunit) * 16);
#pragma unroll
            for (int bb2 = 0; bb2 < 2; bb2++) {
                uint32_t r0, r1, r2, r3;
                ldmat4(r0, r1, r2, r3,
                       sB + (wn * 32 + bb2 * 16 + lmrow) * GROWB + (kb * 2 + lmunit) * 16);
#pragma unroll
                for (int am = 0; am < 4; am++) {
                    mma16816h(acc[am][bb2 * 2],     a[am][0], a[am][1], a[am][2], a[am][3], r0, r2);
                    mma16816h(acc[am][bb2 * 2 + 1], a[am][0], a[am][1], a[am][2], a[am][3], r1, r3);
                }
            }
        }
    }

    const int g = lane >> 2, it = lane & 3;
#pragma unroll
    for (int am = 0; am < 4; am++) {
        const int row0 = m0 + wm * 64 + am * 16 + g;
#pragma unroll
        for (int bn = 0; bn < 4; bn++) {
            const int col = n0 + wn * 32 + bn * 8 + it * 2;
            if (EP == 0) {
                float* p0 = (float*)OUT + (size_t)row0 * 1024 + col;
                float* p1 = p0 + 8 * 1024;
                *(float2*)p0 = make_float2(acc[am][bn][0], acc[am][bn][1]);
                *(float2*)p1 = make_float2(acc[am][bn][2], acc[am][bn][3]);
            } else {
                const int h = col >> 6, d = col & 63;
#pragma unroll
                for (int half_i = 0; half_i < 2; half_i++) {
                    __half2 hv = __floats2half2_rn(acc[am][bn][half_i * 2],
                                                   acc[am][bn][half_i * 2 + 1]);
                    __half* op = (__half*)OUT
                        + (size_t)(row0 + half_i * 8) * 1024 + h * 64 + d;
                    *(__half2*)op = hv;
                }
            }
        }
    }
}

// ================= HMMA flash attention: bf16-split QK + fp16 single-term PV =========
#define TROW 272
#define QSZ (128 * TROW)                 // 34816
#define KVSUB (64 * TROW)                // 17408
#define VROW 144
#define VSUB (64 * VROW)                 // 9216
#define KVSTRIDE (KVSUB + VSUB)          // 26624
#define ATTN_SMEM (QSZ + 2 * KVSTRIDE)   // 88064

__global__ __launch_bounds__(256, 2)
void attn_tc(const float* __restrict__ mask,
             const __nv_bfloat16* __restrict__ Q2,
             const __nv_bfloat16* __restrict__ K2,
             const __half* __restrict__ Vh,
             __half* __restrict__ Aout) {
    extern __shared__ __align__(128) char smc[];
    const uint32_t sq = smem_u32(smc);

    const int tid = threadIdx.x;
    const int wid = tid >> 5;
    const int lane = tid & 31;
    const int g = lane >> 2, it = lane & 3;
    const int lmrow = ((lane >> 3) & 1) * 8 + (lane & 7);
    const int lmunit = lane >> 4;

    const int b = blockIdx.z, h = blockIdx.y;
    const int q0 = blockIdx.x * 128;
    const size_t brow = (size_t)b * SS;

#pragma unroll
    for (int i = 0; i < 8; i++) {
        int idx = tid + i * 256;
        int u = idx & 15, r = idx >> 4;
        cp16(sq + r * TROW + u * 16, Q2 + (brow + q0 + r) * 2048 + h * 128 + u * 8);
    }
    cp_commit();

#pragma unroll
    for (int i = 0; i < 4; i++) {
        int idx = tid + i * 256;
        int u = idx & 15, r = idx >> 4;
        cp16(sq + QSZ + r * TROW + u * 16, K2 + (brow + r) * 2048 + h * 128 + u * 8);
    }
#pragma unroll
    for (int i = 0; i < 2; i++) {
        int idx = tid + i * 256;
        int u = idx & 7, r = idx >> 3;
        cp16(sq + QSZ + KVSUB + r * VROW + u * 16, Vh + (brow + r) * 1024 + h * 64 + u * 8);
    }
    cp_commit();

    float o[8][4];
#pragma unroll
    for (int dn = 0; dn < 8; dn++)
#pragma unroll
        for (int j = 0; j < 4; j++) o[dn][j] = 0.f;
    float mst0 = -INFINITY, mst1 = -INFINITY, l0 = 0.f, l1 = 0.f;

    const float* mrow0 = mask + ((size_t)b * SS + q0 + wid * 16 + g) * SS;
    const float* mrow1 = mrow0 + 8 * SS;

    uint32_t qh[4][4];
    bool qh_loaded = false;

    for (int st = 0; st < 32; st++) {
        const int cur = st & 1;
        cp_wait<0>();
        __syncthreads();

        if (st + 1 < 32) {
            const uint32_t kb = sq + QSZ + (uint32_t)(cur ^ 1) * KVSTRIDE;
            const size_t gbase = brow + (size_t)(st + 1) * 64;
#pragma unroll
            for (int i = 0; i < 4; i++) {
                int idx = tid + i * 256;
                int u = idx & 15, r = idx >> 4;
                cp16(kb + r * TROW + u * 16, K2 + (gbase + r) * 2048 + h * 128 + u * 8);
            }
#pragma unroll
            for (int i = 0; i < 2; i++) {
                int idx = tid + i * 256;
                int u = idx & 7, r = idx >> 3;
                cp16(kb + KVSUB + r * VROW + u * 16, Vh + (gbase + r) * 1024 + h * 64 + u * 8);
            }
            cp_commit();
        }

        if (!qh_loaded) {
            qh_loaded = true;
#pragma unroll
            for (int u4 = 0; u4 < 4; u4++)
                ldmat4(qh[u4][0], qh[u4][1], qh[u4][2], qh[u4][3],
                       sq + (wid * 16 + lmrow) * TROW + (u4 * 2 + lmunit) * 16);
        }

        const uint32_t sk = sq + QSZ + (uint32_t)cur * KVSTRIDE;
        const uint32_t sv = sk + KVSUB;

        float s[8][4];
#pragma unroll
        for (int nb = 0; nb < 8; nb++)
#pragma unroll
            for (int j = 0; j < 4; j++) s[nb][j] = 0.f;

#pragma unroll
        for (int u4 = 0; u4 < 4; u4++) {
            uint32_t ql0, ql1, ql2, ql3;
            ldmat4(ql0, ql1, ql2, ql3,
                   sq + (wid * 16 + lmrow) * TROW + (8 + u4 * 2 + lmunit) * 16);
#pragma unroll
            for (int nb16 = 0; nb16 < 4; nb16++) {
                uint32_t r0, r1, r2, r3;
                ldmat4(r0, r1, r2, r3,
                       sk + (nb16 * 16 + lmrow) * TROW + (u4 * 2 + lmunit) * 16);
                mma16816(s[nb16 * 2],     qh[u4][0], qh[u4][1], qh[u4][2], qh[u4][3], r0, r2);
                mma16816(s[nb16 * 2 + 1], qh[u4][0], qh[u4][1], qh[u4][2], qh[u4][3], r1, r3);
                mma16816(s[nb16 * 2],     ql0, ql1, ql2, ql3, r0, r2);
                mma16816(s[nb16 * 2 + 1], ql0, ql1, ql2, ql3, r1, r3);
            }
#pragma unroll
            for (int nb16 = 0; nb16 < 4; nb16++) {
                uint32_t r0, r1, r2, r3;
                ldmat4(r0, r1, r2, r3,
                       sk + (nb16 * 16 + lmrow) * TROW + (8 + u4 * 2 + lmunit) * 16);
                mma16816(s[nb16 * 2],     qh[u4][0], qh[u4][1], qh[u4][2], qh[u4][3], r0, r2);
                mma16816(s[nb16 * 2 + 1], qh[u4][0], qh[u4][1], qh[u4][2], qh[u4][3], r1, r3);
            }
        }

        float mx0 = -INFINITY, mx1 = -INFINITY;
#pragma unroll
        for (int nb = 0; nb < 8; nb++) {
            const int col = st * 64 + nb * 8 + it * 2;
            float2 m0 = *(const float2*)(mrow0 + col);
            float2 m1 = *(const float2*)(mrow1 + col);
            s[nb][0] = fmaf(s[nb][0], 0.125f, m0.x);
            s[nb][1] = fmaf(s[nb][1], 0.125f, m0.y);
            s[nb][2] = fmaf(s[nb][2], 0.125f, m1.x);
            s[nb][3] = fmaf(s[nb][3], 0.125f, m1.y);
            mx0 = fmaxf(mx0, fmaxf(s[nb][0], s[nb][1]));
            mx1 = fmaxf(mx1, fmaxf(s[nb][2], s[nb][3]));
        }
        mx0 = fmaxf(mx0, __shfl_xor_sync(0xffffffffu, mx0, 1));
        mx0 = fmaxf(mx0, __shfl_xor_sync(0xffffffffu, mx0, 2));
        mx1 = fmaxf(mx1, __shfl_xor_sync(0xffffffffu, mx1, 1));
        mx1 = fmaxf(mx1, __shfl_xor_sync(0xffffffffu, mx1, 2));

        const float nm0 = fmaxf(mst0, mx0), nm1 = fmaxf(mst1, mx1);
        const float corr0 = __expf(mst0 - nm0), corr1 = __expf(mst1 - nm1);
        mst0 = nm0; mst1 = nm1;

        uint32_t ph[16];
        float sum0 = 0.f, sum1 = 0.f;
#pragma unroll
        for (int nb = 0; nb < 8; nb++) {
            float p0 = __expf(s[nb][0] - nm0);
            float p1 = __expf(s[nb][1] - nm0);
            float p2 = __expf(s[nb][2] - nm1);
            float p3 = __expf(s[nb][3] - nm1);
            sum0 += p0 + p1; sum1 += p2 + p3;
            const int u = nb >> 1;
            const int base = u * 4 + (nb & 1) * 2;
            ph[base]     = pack_h2(p0, p1);
            ph[base + 1] = pack_h2(p2, p3);
        }
        sum0 += __shfl_xor_sync(0xffffffffu, sum0, 1);
        sum0 += __shfl_xor_sync(0xffffffffu, sum0, 2);
        sum1 += __shfl_xor_sync(0xffffffffu, sum1, 1);
        sum1 += __shfl_xor_sync(0xffffffffu, sum1, 2);
        l0 = l0 * corr0 + sum0;
        l1 = l1 * corr1 + sum1;
#pragma unroll
        for (int dn = 0; dn < 8; dn++) {
            o[dn][0] *= corr0; o[dn][1] *= corr0;
            o[dn][2] *= corr1; o[dn][3] *= corr1;
        }

#pragma unroll
        for (int u = 0; u < 4; u++) {
            const uint32_t* ap = ph + u * 4;
#pragma unroll
            for (int dn16 = 0; dn16 < 4; dn16++) {
                uint32_t r0, r1, r2, r3;
                ldmat4t(r0, r1, r2, r3,
                        sv + (u * 16 + lmrow) * VROW + (dn16 * 2 + lmunit) * 16);
                mma16816h(o[dn16 * 2],     ap[0], ap[1], ap[2], ap[3], r0, r1);
                mma16816h(o[dn16 * 2 + 1], ap[0], ap[1], ap[2], ap[3], r2, r3);
            }
        }
    }

    // ---- epilogue: normalize, write fp16 single [row][1024] ----
    const float inv0 = 1.f / l0, inv1 = 1.f / l1;
    const size_t row0 = brow + q0 + wid * 16 + g;
#pragma unroll
    for (int dn = 0; dn < 8; dn++) {
        const int col = h * 64 + dn * 8 + it * 2;
        __half2 a01 = __floats2half2_rn(o[dn][0] * inv0, o[dn][1] * inv0);
        __half2 a23 = __floats2half2_rn(o[dn][2] * inv1, o[dn][3] * inv1);
        *(__half2*)(Aout + row0 * 1024 + col) = a01;
        *(__half2*)(Aout + (row0 + 8) * 1024 + col) = a23;
    }
}

// ---------------- launch ----------------
extern "C" void kernel_launch(void* const* d_in, const int* in_sizes, int n_in,
                              void* d_out, int out_size) {
    (void)in_sizes; (void)n_in; (void)out_size;
    const float* hidden = (const float*)d_in[0];
    const float* mask   = (const float*)d_in[1];
    const float* qs = (const float*)d_in[2];
    const float* qd = (const float*)d_in[3];
    const float* ks = (const float*)d_in[4];
    const float* kd = (const float*)d_in[5];
    const float* vs = (const float*)d_in[6];
    const float* vd = (const float*)d_in[7];
    const float* os = (const float*)d_in[8];
    const float* od = (const float*)d_in[9];

    __nv_bfloat16 *a2, *wq2, *wk2, *q2, *k2;
    __half *ah, *wvh, *woh, *vh;
    cudaGetSymbolAddress((void**)&a2,  g_a2);
    cudaGetSymbolAddress((void**)&ah,  g_ah);
    cudaGetSymbolAddress((void**)&wq2, g_wq2);
    cudaGetSymbolAddress((void**)&wk2, g_wk2);
    cudaGetSymbolAddress((void**)&wvh, g_wvh);
    cudaGetSymbolAddress((void**)&woh, g_woh);
    cudaGetSymbolAddress((void**)&q2,  g_q2);
    cudaGetSymbolAddress((void**)&k2,  g_k2);
    cudaGetSymbolAddress((void**)&vh,  g_vh);

    cudaFuncSetAttribute(tc_gemm, cudaFuncAttributeMaxDynamicSharedMemorySize, GSMEM);
    cudaFuncSetAttribute(tc_gemm_h<0>, cudaFuncAttributeMaxDynamicSharedMemorySize, GSMEM);
    cudaFuncSetAttribute(tc_gemm_h<1>, cudaFuncAttributeMaxDynamicSharedMemorySize, GSMEM);
    cudaFuncSetAttribute(attn_tc, cudaFuncAttributeMaxDynamicSharedMemorySize, ATTN_SMEM);

    // fused prep
    prep_kernel<<<dim3(1024, 5), 256>>>(hidden, qs, qd, ks, kd, vs, vd, os, od,
                                        a2, ah, wq2, wk2, wvh, woh);

    // Q,K projections (bf16 3-term)
    tc_gemm<<<dim3(8, 16, 2), 512, GSMEM>>>(a2, wq2, wk2, q2, k2);

    // V projection (fp16 2-term) -> per-head fp16
    tc_gemm_h<1><<<dim3(8, 16, 1), 512, GSMEM>>>(ah, wvh, vh);

    // attention -> fp16 single output into g_ah (reused)
    attn_tc<<<dim3(SS / 128, NHH, BB), 256, ATTN_SMEM>>>(mask, q2, k2, vh, ah);

    // O projection (fp16 2-term) -> fp32 d_out
    tc_gemm_h<0><<<dim3(8, 16, 1), 512, GSMEM>>>(ah, woh, d_out);
}